// round 6
// baseline (speedup 1.0000x reference)
#include <cuda_runtime.h>
#include <cuda_bf16.h>
#include <math.h>
#include <stdint.h>

// ---------------- problem constants ----------------
#define LNUM  6
#define D     1024
#define H     16
#define DKH   64
#define FFD   4096
#define TT    1024
#define BATCH 2
#define NTOK  2048
#define D3    3072
#define D2    2048
#define ATT_SCALE 0.125f

#define SWZ(o) ((o) ^ (((o) >> 3) & 0x70))

// ---------------- scratch (device globals; no allocs allowed) ----------------
__device__ float g_x   [NTOK*D];     // residual stream (f32)
__device__ float g_qkv [NTOK*D3];
__device__ float g_gate[NTOK*D3];
__device__ __nv_bfloat16 g_chi[NTOK*D2],  g_clo[NTOK*D2];   // concat [x,y] hi/lo
__device__ __nv_bfloat16 g_lhi[NTOK*D],   g_llo[NTOK*D];    // LN output hi/lo
__device__ __nv_bfloat16 g_phi[NTOK*D],   g_plo[NTOK*D];    // attn output hi/lo
__device__ __nv_bfloat16 g_fhi[NTOK*FFD], g_flo[NTOK*FFD];  // FF hidden hi/lo
__device__ __nv_bfloat16 g_xhi[NTOK*D],   g_xlo[NTOK*D];    // input x split
__device__ __nv_bfloat16 wb_in_hi [D*D],        wb_in_lo [D*D];
__device__ __nv_bfloat16 wb_qkv_hi[LNUM*D3*D],  wb_qkv_lo[LNUM*D3*D];
__device__ __nv_bfloat16 wb_out_hi[LNUM*D*D],   wb_out_lo[LNUM*D*D];
__device__ __nv_bfloat16 wb_f1_hi [LNUM*FFD*D], wb_f1_lo [LNUM*FFD*D];
__device__ __nv_bfloat16 wb_f2_hi [LNUM*D*FFD], wb_f2_lo [LNUM*D*FFD];
__device__ __nv_bfloat16 wb_g1_hi [LNUM*D3*D2], wb_g1_lo [LNUM*D3*D2];
__device__ __nv_bfloat16 wb_g2_hi [LNUM*D3*D2], wb_g2_lo [LNUM*D3*D2];

// ---------------- PTX helpers (portable: sm_80-level) ----------------
__device__ __forceinline__ uint32_t smem_u32(const void* p) {
    uint32_t a;
    asm("{ .reg .u64 t; cvta.to.shared.u64 t, %1; cvt.u32.u64 %0, t; }" : "=r"(a) : "l"(p));
    return a;
}
__device__ __forceinline__ void cp16(uint32_t d, const void* g) {
    asm volatile("cp.async.cg.shared.global [%0], [%1], 16;" :: "r"(d), "l"(g));
}
__device__ __forceinline__ void ldm_x4(uint32_t* f, uint32_t addr) {
    asm volatile("ldmatrix.sync.aligned.m8n8.x4.shared.b16 {%0,%1,%2,%3}, [%4];"
                 : "=r"(f[0]), "=r"(f[1]), "=r"(f[2]), "=r"(f[3]) : "r"(addr));
}
__device__ __forceinline__ void mma16816(float* c, const uint32_t* a, uint32_t b0, uint32_t b1) {
    asm volatile(
        "mma.sync.aligned.m16n8k16.row.col.f32.bf16.bf16.f32 "
        "{%0,%1,%2,%3}, {%4,%5,%6,%7}, {%8,%9}, {%0,%1,%2,%3};"
        : "+f"(c[0]), "+f"(c[1]), "+f"(c[2]), "+f"(c[3])
        : "r"(a[0]), "r"(a[1]), "r"(a[2]), "r"(a[3]), "r"(b0), "r"(b1));
}
__device__ __forceinline__ float gelu_exact(float v) { return v * normcdff(v); }
__device__ __forceinline__ void split_bf16(float v, __nv_bfloat16& h, __nv_bfloat16& l) {
    h = __float2bfloat16(v);
    l = __float2bfloat16(v - __bfloat162float(h));
}

// ---------------- bf16 hi/lo split GEMM v3 (3-stage pipeline, 1 sync) --------
// C[NTOK,ncols] = A[NTOK,K] @ W[ncols,K]^T (3-term hi/lo accumulation)
// mode 0: Cf = result (+bias), leading dim ldc.
// mode 1: gelu(result+bias) -> hi/lo bf16 at ldc.
// mode 2: result+bias      -> hi/lo bf16 at ldc.
#define STAGE_B 65536
#define NSTAGE  3
#define SMEM_BYTES (NSTAGE*STAGE_B)

__global__ __launch_bounds__(256)
void gemm_mma(const __nv_bfloat16* __restrict__ Ahi, const __nv_bfloat16* __restrict__ Alo,
              int lda,
              const __nv_bfloat16* __restrict__ Whi, const __nv_bfloat16* __restrict__ Wlo,
              const float* __restrict__ bias,
              float* __restrict__ Cf,
              __nv_bfloat16* __restrict__ Chi, __nv_bfloat16* __restrict__ Clo,
              int ldc, int K, int mode)
{
    extern __shared__ char smem[];
    const uint32_t sb = smem_u32(smem);
    const int tid  = threadIdx.x;
    const int wid  = tid >> 5;
    const int lane = tid & 31;
    const int wm   = wid >> 1;
    const int wn   = wid & 1;
    const int row0 = blockIdx.y * 128;
    const int col0 = blockIdx.x * 128;

    float acc[2][8][4];
#pragma unroll
    for (int i = 0; i < 2; i++)
#pragma unroll
        for (int g = 0; g < 8; g++)
#pragma unroll
            for (int q = 0; q < 4; q++) acc[i][g][q] = 0.f;

    const int lr   = lane & 15;
    const int koff = (lane >> 4) << 4;
    uint32_t roffA[2], rxA[2], roffB[4], rxB[4];
#pragma unroll
    for (int i = 0; i < 2; i++) {
        int r = wm * 32 + i * 16 + lr;
        roffA[i] = r * 128; rxA[i] = (r & 7) << 4;
    }
#pragma unroll
    for (int j = 0; j < 4; j++) {
        int r = wn * 64 + j * 16 + lr;
        roffB[j] = r * 128; rxB[j] = (r & 7) << 4;
    }

    const int nch = K / 64;
    const int ldr = tid >> 3, ldc4 = tid & 7;                 // loader mapping

    auto issue = [&](int cc, int stage) {
        const int kbase = cc * 64;
        const uint32_t st = sb + stage * STAGE_B;
#pragma unroll
        for (int i = 0; i < 4; i++) {
            int r = ldr + i * 32;
            uint32_t off = SWZ((uint32_t)(r * 128 + ldc4 * 16));
            size_t sa = (size_t)(row0 + r) * lda + kbase + ldc4 * 8;
            size_t sw = (size_t)(col0 + r) * K   + kbase + ldc4 * 8;
            cp16(st +         off, Ahi + sa);
            cp16(st + 16384 + off, Alo + sa);
            cp16(st + 32768 + off, Whi + sw);
            cp16(st + 49152 + off, Wlo + sw);
        }
        asm volatile("cp.async.commit_group;");
    };

    issue(0, 0);
    issue(1, 1);
    for (int cc = 0; cc < nch; cc++) {
        asm volatile("cp.async.wait_group 1;");   // chunk cc arrived
        __syncthreads();                          // all warps past compute(cc-1)
        if (cc + 2 < nch) issue(cc + 2, (cc + 2) % NSTAGE);

        const uint32_t AH = sb + (cc % NSTAGE) * STAGE_B;
        const uint32_t AL = AH + 16384;
        const uint32_t WHs = AH + 32768;
        const uint32_t WLs = AH + 49152;
#pragma unroll
        for (int ks = 0; ks < 4; ks++) {
            const uint32_t kb = ks * 32 + koff;
            uint32_t ah[2][4], al[2][4];
#pragma unroll
            for (int i = 0; i < 2; i++) {
                ldm_x4(ah[i], AH + roffA[i] + (kb ^ rxA[i]));
                ldm_x4(al[i], AL + roffA[i] + (kb ^ rxA[i]));
            }
#pragma unroll
            for (int j = 0; j < 4; j++) {
                uint32_t bh[4], bl[4];
                ldm_x4(bh, WHs + roffB[j] + (kb ^ rxB[j]));
                ldm_x4(bl, WLs + roffB[j] + (kb ^ rxB[j]));
#pragma unroll
                for (int i = 0; i < 2; i++) {
                    mma16816(acc[i][j*2+0], ah[i], bh[0], bh[2]);
                    mma16816(acc[i][j*2+1], ah[i], bh[1], bh[3]);
                    mma16816(acc[i][j*2+0], ah[i], bl[0], bl[2]);
                    mma16816(acc[i][j*2+1], ah[i], bl[1], bl[3]);
                    mma16816(acc[i][j*2+0], al[i], bh[0], bh[2]);
                    mma16816(acc[i][j*2+1], al[i], bh[1], bh[3]);
                }
            }
        }
    }

    const int rbase = row0 + wm * 32 + (lane >> 2);
    const int cbase = wn * 64 + (lane & 3) * 2;
#pragma unroll
    for (int i = 0; i < 2; i++) {
#pragma unroll
        for (int g = 0; g < 8; g++) {
            const int c  = cbase + g * 8;
            const int cg = col0 + c;
            const int r0 = rbase + i * 16;
            float b0 = bias ? bias[cg]     : 0.f;
            float b1 = bias ? bias[cg + 1] : 0.f;
            float v00 = acc[i][g][0] + b0, v01 = acc[i][g][1] + b1;
            float v10 = acc[i][g][2] + b0, v11 = acc[i][g][3] + b1;
            if (mode == 0) {
                *(float2*)(Cf + (size_t)r0 * ldc + cg)     = make_float2(v00, v01);
                *(float2*)(Cf + (size_t)(r0+8) * ldc + cg) = make_float2(v10, v11);
            } else {
                if (mode == 1) {
                    v00 = gelu_exact(v00); v01 = gelu_exact(v01);
                    v10 = gelu_exact(v10); v11 = gelu_exact(v11);
                }
                __nv_bfloat16 h00, l00, h01, l01, h10, l10, h11, l11;
                split_bf16(v00, h00, l00); split_bf16(v01, h01, l01);
                split_bf16(v10, h10, l10); split_bf16(v11, h11, l11);
                *(__nv_bfloat162*)(Chi + (size_t)r0 * ldc + cg)     = __halves2bfloat162(h00, h01);
                *(__nv_bfloat162*)(Chi + (size_t)(r0+8) * ldc + cg) = __halves2bfloat162(h10, h11);
                *(__nv_bfloat162*)(Clo + (size_t)r0 * ldc + cg)     = __halves2bfloat162(l00, l01);
                *(__nv_bfloat162*)(Clo + (size_t)(r0+8) * ldc + cg) = __halves2bfloat162(l10, l11);
            }
        }
    }
}

// ---------------- flash-style tiled attention (fp32, hi/lo bf16 out) ---------
#define QTILE 128
#define KTILE 64
#define QP 68
#define KP 68
#define VP 68
#define SP 68
#define AQ_OFF 0
#define AK_OFF (AQ_OFF + 128*QP)
#define AV_OFF (AK_OFF + 64*KP)
#define AS_OFF (AV_OFF + 64*VP)
#define AM_OFF (AS_OFF + 128*SP)
#define AL_OFF (AM_OFF + 128)
#define AF_OFF (AL_OFF + 128)
#define AR_OFF (AF_OFF + 128)
#define ATTN_SMEM ((AR_OFF + 256) * 4)

__global__ __launch_bounds__(256)
void attn_flash(const float* __restrict__ qkv,
                __nv_bfloat16* __restrict__ ahi, __nv_bfloat16* __restrict__ alo) {
    extern __shared__ float sm[];
    float* Qs = sm + AQ_OFF;
    float* Kt = sm + AK_OFF;
    float* Vs = sm + AV_OFF;
    float* Ss = sm + AS_OFF;
    float* Mm = sm + AM_OFF;
    float* Ll = sm + AL_OFF;
    float* Fs = sm + AF_OFF;
    float* Red = sm + AR_OFF;

    const int tid = threadIdx.x;
    const int tx = tid & 15, ty = tid >> 4;
    const int bh = blockIdx.y;
    const int b  = bh >> 4;
    const int h  = bh & 15;
    const int q0 = blockIdx.x * QTILE;

#pragma unroll
    for (int i = 0; i < 8; i++) {
        int idx = tid + i * 256;
        int r = idx >> 4, c = idx & 15;
        float4 v = *(const float4*)(qkv + ((size_t)((q0 + r) * BATCH + b)) * D3 + h * DKH + c * 4);
        v.x *= ATT_SCALE; v.y *= ATT_SCALE; v.z *= ATT_SCALE; v.w *= ATT_SCALE;
        *(float4*)(Qs + r * QP + c * 4) = v;
    }
    if (tid < 128) { Mm[tid] = -1e30f; Ll[tid] = 0.f; }

    float acc[8][4];
#pragma unroll
    for (int i = 0; i < 8; i++)
#pragma unroll
        for (int j = 0; j < 4; j++) acc[i][j] = 0.f;

    __syncthreads();

    const int ntiles = blockIdx.x * 2 + 2;
    const int qred = tid >> 1, hf = tid & 1;

    for (int kt = 0; kt < ntiles; kt++) {
        const int s0 = kt * KTILE;
#pragma unroll
        for (int i = 0; i < 4; i++) {
            int idx = tid + i * 256;
            int r = idx >> 4, c = idx & 15;
            const float* base = qkv + ((size_t)((s0 + r) * BATCH + b)) * D3 + h * DKH + c * 4;
            float4 kv = *(const float4*)(base + D);
            float4 vv = *(const float4*)(base + 2 * D);
            Kt[(c*4+0) * KP + r] = kv.x;
            Kt[(c*4+1) * KP + r] = kv.y;
            Kt[(c*4+2) * KP + r] = kv.z;
            Kt[(c*4+3) * KP + r] = kv.w;
            *(float4*)(Vs + r * VP + c * 4) = vv;
        }
        __syncthreads();

        float sreg[8][4];
#pragma unroll
        for (int i = 0; i < 8; i++)
#pragma unroll
            for (int j = 0; j < 4; j++) sreg[i][j] = 0.f;
#pragma unroll 8
        for (int d = 0; d < 64; d++) {
            const float4 kq = *(const float4*)(Kt + d * KP + tx * 4);
#pragma unroll
            for (int i = 0; i < 8; i++) {
                float qv = Qs[(ty * 8 + i) * QP + d];
                sreg[i][0] += qv * kq.x;
                sreg[i][1] += qv * kq.y;
                sreg[i][2] += qv * kq.z;
                sreg[i][3] += qv * kq.w;
            }
        }
#pragma unroll
        for (int i = 0; i < 8; i++) {
            const int qg = q0 + ty * 8 + i;
            float4 o;
            o.x = (s0 + tx*4 + 0 > qg) ? -1e30f : sreg[i][0];
            o.y = (s0 + tx*4 + 1 > qg) ? -1e30f : sreg[i][1];
            o.z = (s0 + tx*4 + 2 > qg) ? -1e30f : sreg[i][2];
            o.w = (s0 + tx*4 + 3 > qg) ? -1e30f : sreg[i][3];
            *(float4*)(Ss + (ty * 8 + i) * SP + tx * 4) = o;
        }
        __syncthreads();

        {
            float mx = -1e30f;
            const float* row = Ss + qred * SP + hf * 32;
#pragma unroll 8
            for (int j = 0; j < 32; j++) mx = fmaxf(mx, row[j]);
            Red[qred * 2 + hf] = mx;
        }
        __syncthreads();
        if (hf == 0) {
            float tm = fmaxf(Red[qred * 2], Red[qred * 2 + 1]);
            float mo = Mm[qred];
            float mn = fmaxf(mo, tm);
            Mm[qred] = mn;
            Fs[qred] = __expf(mo - mn);
        }
        __syncthreads();
        {
            const float mq = Mm[qred];
            float* row = Ss + qred * SP + hf * 32;
            float sum = 0.f;
#pragma unroll 8
            for (int j = 0; j < 32; j++) {
                float e = __expf(row[j] - mq);
                row[j] = e; sum += e;
            }
            Red[qred * 2 + hf] = sum;
        }
        __syncthreads();
        if (hf == 0)
            Ll[qred] = Ll[qred] * Fs[qred] + Red[qred * 2] + Red[qred * 2 + 1];

#pragma unroll
        for (int i = 0; i < 8; i++) {
            const float f = Fs[ty * 8 + i];
#pragma unroll
            for (int j = 0; j < 4; j++) acc[i][j] *= f;
        }
#pragma unroll 4
        for (int s = 0; s < 64; s++) {
            const float4 v4 = *(const float4*)(Vs + s * VP + tx * 4);
#pragma unroll
            for (int i = 0; i < 8; i++) {
                const float p = Ss[(ty * 8 + i) * SP + s];
                acc[i][0] += p * v4.x;
                acc[i][1] += p * v4.y;
                acc[i][2] += p * v4.z;
                acc[i][3] += p * v4.w;
            }
        }
        __syncthreads();
    }

#pragma unroll
    for (int i = 0; i < 8; i++) {
        const int q = ty * 8 + i;
        const float inv = 1.f / Ll[q];
        float v0 = acc[i][0] * inv, v1 = acc[i][1] * inv;
        float v2 = acc[i][2] * inv, v3 = acc[i][3] * inv;
        __nv_bfloat16 h0, l0, h1, l1, h2, l2, h3, l3;
        split_bf16(v0, h0, l0); split_bf16(v1, h1, l1);
        split_bf16(v2, h2, l2); split_bf16(v3, h3, l3);
        size_t base = ((size_t)((q0 + q) * BATCH + b)) * D + h * DKH + tx * 4;
        *(__nv_bfloat162*)(ahi + base)     = __halves2bfloat162(h0, h1);
        *(__nv_bfloat162*)(ahi + base + 2) = __halves2bfloat162(h2, h3);
        *(__nv_bfloat162*)(alo + base)     = __halves2bfloat162(l0, l1);
        *(__nv_bfloat162*)(alo + base + 2) = __halves2bfloat162(l2, l3);
    }
}

// ---------------- fused GRU + LN + splits (one block per token) --------------
__global__ __launch_bounds__(256)
void gru_ln_split(float* __restrict__ px, const float* __restrict__ gate,
                  const float* __restrict__ bg,
                  const float* __restrict__ g, const float* __restrict__ b,
                  __nv_bfloat16* __restrict__ cathi, __nv_bfloat16* __restrict__ catlo,
                  __nv_bfloat16* __restrict__ lnhi, __nv_bfloat16* __restrict__ lnlo,
                  float* __restrict__ outf) {
    const int n = blockIdx.x;
    const int tid = threadIdx.x;
    const float* grow = gate + (size_t)n * D3;
    float vals[4];
    float s = 0.f, sq = 0.f;
#pragma unroll
    for (int k = 0; k < 4; k++) {
        const int j = tid + k * 256;
        float gr = grow[j];
        float gz = grow[D + j];
        float gh = grow[2 * D + j];
        float r = 1.f / (1.f + __expf(-gr));
        float z = 1.f / (1.f + __expf(-(gz - bg[j])));
        float hh = tanhf(gh * r);
        float xv = px[(size_t)n * D + j];
        float v = (1.f - z) * xv + z * hh;
        px[(size_t)n * D + j] = v;
        vals[k] = v;
        __nv_bfloat16 h, l; split_bf16(v, h, l);
        cathi[(size_t)n * D2 + j] = h;
        catlo[(size_t)n * D2 + j] = l;
        s += v; sq += v * v;
    }
    __shared__ float rs[256], rq[256];
    rs[tid] = s; rq[tid] = sq; __syncthreads();
    for (int off = 128; off > 0; off >>= 1) {
        if (tid < off) { rs[tid] += rs[tid + off]; rq[tid] += rq[tid + off]; }
        __syncthreads();
    }
    const float mu  = rs[0] * (1.f / D);
    const float var = rq[0] * (1.f / D) - mu * mu;
    const float inv = rsqrtf(var + 1e-6f);
#pragma unroll
    for (int k = 0; k < 4; k++) {
        const int j = tid + k * 256;
        float y = (vals[k] - mu) * inv * g[j] + b[j];
        if (outf) {
            outf[(size_t)n * D + j] = y;
        } else {
            __nv_bfloat16 h, l; split_bf16(y, h, l);
            lnhi[(size_t)n * D + j] = h;
            lnlo[(size_t)n * D + j] = l;
        }
    }
}

// ---------------- fused GELU+PE + LN + splits (layer-0 entry) ----------------
__global__ __launch_bounds__(256)
void gelu_pe_ln_split(float* __restrict__ px, const float* __restrict__ pe,
                      const float* __restrict__ g, const float* __restrict__ b,
                      __nv_bfloat16* __restrict__ cathi, __nv_bfloat16* __restrict__ catlo,
                      __nv_bfloat16* __restrict__ lnhi, __nv_bfloat16* __restrict__ lnlo) {
    const int n = blockIdx.x;
    const int t = n >> 1;
    const int tid = threadIdx.x;
    float vals[4];
    float s = 0.f, sq = 0.f;
#pragma unroll
    for (int k = 0; k < 4; k++) {
        const int j = tid + k * 256;
        float v = gelu_exact(px[(size_t)n * D + j]) + pe[(size_t)t * D + j];
        px[(size_t)n * D + j] = v;
        vals[k] = v;
        __nv_bfloat16 h, l; split_bf16(v, h, l);
        cathi[(size_t)n * D2 + j] = h;
        catlo[(size_t)n * D2 + j] = l;
        s += v; sq += v * v;
    }
    __shared__ float rs[256], rq[256];
    rs[tid] = s; rq[tid] = sq; __syncthreads();
    for (int off = 128; off > 0; off >>= 1) {
        if (tid < off) { rs[tid] += rs[tid + off]; rq[tid] += rq[tid + off]; }
        __syncthreads();
    }
    const float mu  = rs[0] * (1.f / D);
    const float var = rq[0] * (1.f / D) - mu * mu;
    const float inv = rsqrtf(var + 1e-6f);
#pragma unroll
    for (int k = 0; k < 4; k++) {
        const int j = tid + k * 256;
        float y = (vals[k] - mu) * inv * g[j] + b[j];
        __nv_bfloat16 h, l; split_bf16(y, h, l);
        lnhi[(size_t)n * D + j] = h;
        lnlo[(size_t)n * D + j] = l;
    }
}

// ---------------- f32 -> hi/lo bf16 split (weights + input) ----------------
__global__ void cvt_split4(const float4* __restrict__ x,
                           __nv_bfloat162* __restrict__ hi, __nv_bfloat162* __restrict__ lo,
                           int n4) {
    int i = blockIdx.x * blockDim.x + threadIdx.x;
    if (i >= n4) return;
    float4 v = x[i];
    __nv_bfloat16 h0, l0, h1, l1, h2, l2, h3, l3;
    split_bf16(v.x, h0, l0); split_bf16(v.y, h1, l1);
    split_bf16(v.z, h2, l2); split_bf16(v.w, h3, l3);
    hi[2*i]   = __halves2bfloat162(h0, h1);
    hi[2*i+1] = __halves2bfloat162(h2, h3);
    lo[2*i]   = __halves2bfloat162(l0, l1);
    lo[2*i+1] = __halves2bfloat162(l2, l3);
}

// ---------------- driver ----------------
extern "C" void kernel_launch(void* const* d_in, const int* in_sizes, int n_in,
                              void* d_out, int out_size) {
    const float* x_in  = (const float*)d_in[0];
    const float* pe    = (const float*)d_in[1];
    const float* in_w  = (const float*)d_in[2];
    const float* in_b  = (const float*)d_in[3];
    const float* qkv_w = (const float*)d_in[4];
    const float* out_w = (const float*)d_in[5];
    const float* out_b = (const float*)d_in[6];
    const float* ln1_g = (const float*)d_in[7];
    const float* ln1_b = (const float*)d_in[8];
    const float* ln2_g = (const float*)d_in[9];
    const float* ln2_b = (const float*)d_in[10];
    const float* ff_w1 = (const float*)d_in[11];
    const float* ff_b1 = (const float*)d_in[12];
    const float* ff_w2 = (const float*)d_in[13];
    const float* ff_b2 = (const float*)d_in[14];
    const float* g1_w  = (const float*)d_in[15];
    const float* g1_bg = (const float*)d_in[16];
    const float* g2_w  = (const float*)d_in[17];
    const float* g2_bg = (const float*)d_in[18];
    const float* on_g  = (const float*)d_in[19];
    const float* on_b  = (const float*)d_in[20];

    float *px, *pqkv, *pgate;
    __nv_bfloat16 *chi, *clo, *lhi, *llo, *phi, *plo, *fhi, *flo, *xhi, *xlo;
    __nv_bfloat16 *w_in_h, *w_in_l, *w_qkv_h, *w_qkv_l, *w_out_h, *w_out_l;
    __nv_bfloat16 *w_f1_h, *w_f1_l, *w_f2_h, *w_f2_l, *w_g1_h, *w_g1_l, *w_g2_h, *w_g2_l;
    cudaGetSymbolAddress((void**)&px,    g_x);
    cudaGetSymbolAddress((void**)&pqkv,  g_qkv);
    cudaGetSymbolAddress((void**)&pgate, g_gate);
    cudaGetSymbolAddress((void**)&chi,   g_chi);  cudaGetSymbolAddress((void**)&clo,   g_clo);
    cudaGetSymbolAddress((void**)&lhi,   g_lhi);  cudaGetSymbolAddress((void**)&llo,   g_llo);
    cudaGetSymbolAddress((void**)&phi,   g_phi);  cudaGetSymbolAddress((void**)&plo,   g_plo);
    cudaGetSymbolAddress((void**)&fhi,   g_fhi);  cudaGetSymbolAddress((void**)&flo,   g_flo);
    cudaGetSymbolAddress((void**)&xhi,   g_xhi);  cudaGetSymbolAddress((void**)&xlo,   g_xlo);
    cudaGetSymbolAddress((void**)&w_in_h,  wb_in_hi);  cudaGetSymbolAddress((void**)&w_in_l,  wb_in_lo);
    cudaGetSymbolAddress((void**)&w_qkv_h, wb_qkv_hi); cudaGetSymbolAddress((void**)&w_qkv_l, wb_qkv_lo);
    cudaGetSymbolAddress((void**)&w_out_h, wb_out_hi); cudaGetSymbolAddress((void**)&w_out_l, wb_out_lo);
    cudaGetSymbolAddress((void**)&w_f1_h,  wb_f1_hi);  cudaGetSymbolAddress((void**)&w_f1_l,  wb_f1_lo);
    cudaGetSymbolAddress((void**)&w_f2_h,  wb_f2_hi);  cudaGetSymbolAddress((void**)&w_f2_l,  wb_f2_lo);
    cudaGetSymbolAddress((void**)&w_g1_h,  wb_g1_hi);  cudaGetSymbolAddress((void**)&w_g1_l,  wb_g1_lo);
    cudaGetSymbolAddress((void**)&w_g2_h,  wb_g2_hi);  cudaGetSymbolAddress((void**)&w_g2_l,  wb_g2_lo);

    cudaFuncSetAttribute(gemm_mma, cudaFuncAttributeMaxDynamicSharedMemorySize, SMEM_BYTES);
    cudaFuncSetAttribute(attn_flash, cudaFuncAttributeMaxDynamicSharedMemorySize, ATTN_SMEM);

    const int EW = 256;
    auto cvtgrid = [](int n) { return (n / 4 + 255) / 256; };

    // ---- weight + input hi/lo splits ----
    cvt_split4<<<cvtgrid(D*D),        EW>>>((const float4*)in_w,  (__nv_bfloat162*)w_in_h,  (__nv_bfloat162*)w_in_l,  D*D/4);
    cvt_split4<<<cvtgrid(LNUM*D3*D),  EW>>>((const float4*)qkv_w, (__nv_bfloat162*)w_qkv_h, (__nv_bfloat162*)w_qkv_l, LNUM*D3*D/4);
    cvt_split4<<<cvtgrid(LNUM*D*D),   EW>>>((const float4*)out_w, (__nv_bfloat162*)w_out_h, (__nv_bfloat162*)w_out_l, LNUM*D*D/4);
    cvt_split4<<<cvtgrid(LNUM*FFD*D), EW>>>((const float4*)ff_w1, (__nv_bfloat162*)w_f1_h,  (__nv_bfloat162*)w_f1_l,  LNUM*FFD*D/4);
    cvt_split4<<<cvtgrid(LNUM*D*FFD), EW>>>((const float4*)ff_w2, (__nv_bfloat162*)w_f2_h,  (__nv_bfloat162*)w_f2_l,  LNUM*D*FFD/4);
    cvt_split4<<<cvtgrid(LNUM*D3*D2), EW>>>((const float4*)g1_w,  (__nv_bfloat162*)w_g1_h,  (__nv_bfloat162*)w_g1_l,  LNUM*D3*D2/4);
    cvt_split4<<<cvtgrid(LNUM*D3*D2), EW>>>((const float4*)g2_w,  (__nv_bfloat162*)w_g2_h,  (__nv_bfloat162*)w_g2_l,  LNUM*D3*D2/4);
    cvt_split4<<<cvtgrid(NTOK*D),     EW>>>((const float4*)x_in,  (__nv_bfloat162*)xhi,     (__nv_bfloat162*)xlo,     NTOK*D/4);

    dim3 gD  (D/128,   NTOK/128);
    dim3 gD3 (D3/128,  NTOK/128);
    dim3 gFF (FFD/128, NTOK/128);

    // ---- input projection, then fused gelu+pe+LN1+splits ----
    gemm_mma<<<gD, 256, SMEM_BYTES>>>(xhi, xlo, D, w_in_h, w_in_l, in_b, px, 0, 0, D, D, 0);
    gelu_pe_ln_split<<<NTOK, 256>>>(px, pe, ln1_g, ln1_b, chi, clo, lhi, llo);

    for (int l = 0; l < LNUM; l++) {
        const __nv_bfloat16* qwh = w_qkv_h + (size_t)l*D3*D;  const __nv_bfloat16* qwl = w_qkv_l + (size_t)l*D3*D;
        const __nv_bfloat16* owh = w_out_h + (size_t)l*D*D;   const __nv_bfloat16* owl = w_out_l + (size_t)l*D*D;
        const __nv_bfloat16* f1h = w_f1_h  + (size_t)l*FFD*D; const __nv_bfloat16* f1l = w_f1_l  + (size_t)l*FFD*D;
        const __nv_bfloat16* f2h = w_f2_h  + (size_t)l*D*FFD; const __nv_bfloat16* f2l = w_f2_l  + (size_t)l*D*FFD;
        const __nv_bfloat16* g1h = w_g1_h  + (size_t)l*D3*D2; const __nv_bfloat16* g1l = w_g1_l  + (size_t)l*D3*D2;
        const __nv_bfloat16* g2h = w_g2_h  + (size_t)l*D3*D2; const __nv_bfloat16* g2l = w_g2_l  + (size_t)l*D3*D2;
        const float* ob  = out_b + (size_t)l*D;
        const float* l2g = ln2_g + (size_t)l*D;  const float* l2b = ln2_b + (size_t)l*D;
        const float* fb1 = ff_b1 + (size_t)l*FFD;
        const float* fb2 = ff_b2 + (size_t)l*D;
        const float* gb1 = g1_bg + (size_t)l*D;
        const float* gb2 = g2_bg + (size_t)l*D;
        const float* ng = (l + 1 < LNUM) ? ln1_g + (size_t)(l+1)*D : on_g;
        const float* nb = (l + 1 < LNUM) ? ln1_b + (size_t)(l+1)*D : on_b;
        float* fout = (l + 1 < LNUM) ? nullptr : (float*)d_out;

        // attention block
        gemm_mma<<<gD3, 256, SMEM_BYTES>>>(lhi, llo, D, qwh, qwl, nullptr, pqkv, 0, 0, D3, D, 0);
        attn_flash<<<dim3(TT/QTILE, BATCH*H), 256, ATTN_SMEM>>>(pqkv, phi, plo);
        gemm_mma<<<gD, 256, SMEM_BYTES>>>(phi, plo, D, owh, owl, ob, 0, chi + D, clo + D, D2, D, 2);
        gemm_mma<<<gD3, 256, SMEM_BYTES>>>(chi, clo, D2, g1h, g1l, nullptr, pgate, 0, 0, D3, D2, 0);
        gru_ln_split<<<NTOK, 256>>>(px, pgate, gb1, l2g, l2b, chi, clo, lhi, llo, nullptr);

        // feed-forward block
        gemm_mma<<<gFF, 256, SMEM_BYTES>>>(lhi, llo, D, f1h, f1l, fb1, 0, fhi, flo, FFD, D, 1);
        gemm_mma<<<gD, 256, SMEM_BYTES>>>(fhi, flo, FFD, f2h, f2l, fb2, 0, chi + D, clo + D, D2, FFD, 2);
        gemm_mma<<<gD3, 256, SMEM_BYTES>>>(chi, clo, D2, g2h, g2l, nullptr, pgate, 0, 0, D3, D2, 0);
        gru_ln_split<<<NTOK, 256>>>(px, pgate, gb2, ng, nb, chi, clo, lhi, llo, fout);
    }
}

// round 7
// speedup vs baseline: 1.0079x; 1.0079x over previous
#include <cuda_runtime.h>
#include <cuda_bf16.h>
#include <math.h>
#include <stdint.h>

// ---------------- problem constants ----------------
#define LNUM  6
#define D     1024
#define H     16
#define DKH   64
#define FFD   4096
#define TT    1024
#define BATCH 2
#define NTOK  2048
#define D3    3072
#define D2    2048
#define ATT_SCALE 0.125f

#define SWZ(o) ((o) ^ (((o) >> 3) & 0x70))

// ---------------- scratch (device globals; no allocs allowed) ----------------
__device__ float g_x   [NTOK*D];     // residual stream (f32)
__device__ float g_qkv [NTOK*D3];
__device__ float g_gate[NTOK*D3];
__device__ __nv_bfloat16 g_chi[NTOK*D2],  g_clo[NTOK*D2];   // concat [x,y] hi/lo
__device__ __nv_bfloat16 g_lhi[NTOK*D],   g_llo[NTOK*D];    // LN output hi/lo
__device__ __nv_bfloat16 g_phi[NTOK*D],   g_plo[NTOK*D];    // attn output hi/lo
__device__ __nv_bfloat16 g_fhi[NTOK*FFD], g_flo[NTOK*FFD];  // FF hidden hi/lo
__device__ __nv_bfloat16 g_xhi[NTOK*D],   g_xlo[NTOK*D];    // input x split
__device__ __nv_bfloat16 wb_in_hi [D*D],        wb_in_lo [D*D];
__device__ __nv_bfloat16 wb_qkv_hi[LNUM*D3*D],  wb_qkv_lo[LNUM*D3*D];
__device__ __nv_bfloat16 wb_out_hi[LNUM*D*D],   wb_out_lo[LNUM*D*D];
__device__ __nv_bfloat16 wb_f1_hi [LNUM*FFD*D], wb_f1_lo [LNUM*FFD*D];
__device__ __nv_bfloat16 wb_f2_hi [LNUM*D*FFD], wb_f2_lo [LNUM*D*FFD];
__device__ __nv_bfloat16 wb_g1_hi [LNUM*D3*D2], wb_g1_lo [LNUM*D3*D2];
__device__ __nv_bfloat16 wb_g2_hi [LNUM*D3*D2], wb_g2_lo [LNUM*D3*D2];

// ---------------- PTX helpers (portable: sm_80-level) ----------------
__device__ __forceinline__ uint32_t smem_u32(const void* p) {
    uint32_t a;
    asm("{ .reg .u64 t; cvta.to.shared.u64 t, %1; cvt.u32.u64 %0, t; }" : "=r"(a) : "l"(p));
    return a;
}
__device__ __forceinline__ void cp16(uint32_t d, const void* g) {
    asm volatile("cp.async.cg.shared.global [%0], [%1], 16;" :: "r"(d), "l"(g));
}
__device__ __forceinline__ void ldm_x4(uint32_t* f, uint32_t addr) {
    asm volatile("ldmatrix.sync.aligned.m8n8.x4.shared.b16 {%0,%1,%2,%3}, [%4];"
                 : "=r"(f[0]), "=r"(f[1]), "=r"(f[2]), "=r"(f[3]) : "r"(addr));
}
__device__ __forceinline__ void mma16816(float* c, const uint32_t* a, uint32_t b0, uint32_t b1) {
    asm volatile(
        "mma.sync.aligned.m16n8k16.row.col.f32.bf16.bf16.f32 "
        "{%0,%1,%2,%3}, {%4,%5,%6,%7}, {%8,%9}, {%0,%1,%2,%3};"
        : "+f"(c[0]), "+f"(c[1]), "+f"(c[2]), "+f"(c[3])
        : "r"(a[0]), "r"(a[1]), "r"(a[2]), "r"(a[3]), "r"(b0), "r"(b1));
}
__device__ __forceinline__ float gelu_exact(float v) { return v * normcdff(v); }
__device__ __forceinline__ void split_bf16(float v, __nv_bfloat16& h, __nv_bfloat16& l) {
    h = __float2bfloat16(v);
    l = __float2bfloat16(v - __bfloat162float(h));
}

// ---------------- bf16 hi/lo split GEMM (R5 config: 2-stage, 1 sync) ---------
#define STAGE_B 65536
#define SMEM_BYTES (2*STAGE_B)

__global__ __launch_bounds__(256)
void gemm_mma(const __nv_bfloat16* __restrict__ Ahi, const __nv_bfloat16* __restrict__ Alo,
              int lda,
              const __nv_bfloat16* __restrict__ Whi, const __nv_bfloat16* __restrict__ Wlo,
              const float* __restrict__ bias,
              float* __restrict__ Cf,
              __nv_bfloat16* __restrict__ Chi, __nv_bfloat16* __restrict__ Clo,
              int ldc, int K, int mode)
{
    extern __shared__ char smem[];
    const uint32_t sb = smem_u32(smem);
    const int tid  = threadIdx.x;
    const int wid  = tid >> 5;
    const int lane = tid & 31;
    const int wm   = wid >> 1;
    const int wn   = wid & 1;
    const int row0 = blockIdx.y * 128;
    const int col0 = blockIdx.x * 128;

    float acc[2][8][4];
#pragma unroll
    for (int i = 0; i < 2; i++)
#pragma unroll
        for (int g = 0; g < 8; g++)
#pragma unroll
            for (int q = 0; q < 4; q++) acc[i][g][q] = 0.f;

    const int lr   = lane & 15;
    const int koff = (lane >> 4) << 4;
    uint32_t roffA[2], rxA[2], roffB[4], rxB[4];
#pragma unroll
    for (int i = 0; i < 2; i++) {
        int r = wm * 32 + i * 16 + lr;
        roffA[i] = r * 128; rxA[i] = (r & 7) << 4;
    }
#pragma unroll
    for (int j = 0; j < 4; j++) {
        int r = wn * 64 + j * 16 + lr;
        roffB[j] = r * 128; rxB[j] = (r & 7) << 4;
    }

    const int nch = K / 64;
    const int ldr = tid >> 3, ldc4 = tid & 7;

    auto issue = [&](int cc, int stage) {
        const int kbase = cc * 64;
        const uint32_t st = sb + stage * STAGE_B;
#pragma unroll
        for (int i = 0; i < 4; i++) {
            int r = ldr + i * 32;
            uint32_t off = SWZ((uint32_t)(r * 128 + ldc4 * 16));
            size_t sa = (size_t)(row0 + r) * lda + kbase + ldc4 * 8;
            size_t sw = (size_t)(col0 + r) * K   + kbase + ldc4 * 8;
            cp16(st +         off, Ahi + sa);
            cp16(st + 16384 + off, Alo + sa);
            cp16(st + 32768 + off, Whi + sw);
            cp16(st + 49152 + off, Wlo + sw);
        }
        asm volatile("cp.async.commit_group;");
    };

    issue(0, 0);
    for (int cc = 0; cc < nch; cc++) {
        const int stage = cc & 1;
        asm volatile("cp.async.wait_group 0;");
        __syncthreads();
        if (cc + 1 < nch) issue(cc + 1, stage ^ 1);

        const uint32_t AH = sb + stage * STAGE_B;
        const uint32_t AL = AH + 16384;
        const uint32_t WHs = AH + 32768;
        const uint32_t WLs = AH + 49152;
#pragma unroll
        for (int ks = 0; ks < 4; ks++) {
            const uint32_t kb = ks * 32 + koff;
            uint32_t ah[2][4], al[2][4];
#pragma unroll
            for (int i = 0; i < 2; i++) {
                ldm_x4(ah[i], AH + roffA[i] + (kb ^ rxA[i]));
                ldm_x4(al[i], AL + roffA[i] + (kb ^ rxA[i]));
            }
#pragma unroll
            for (int j = 0; j < 4; j++) {
                uint32_t bh[4], bl[4];
                ldm_x4(bh, WHs + roffB[j] + (kb ^ rxB[j]));
                ldm_x4(bl, WLs + roffB[j] + (kb ^ rxB[j]));
#pragma unroll
                for (int i = 0; i < 2; i++) {
                    mma16816(acc[i][j*2+0], ah[i], bh[0], bh[2]);
                    mma16816(acc[i][j*2+1], ah[i], bh[1], bh[3]);
                    mma16816(acc[i][j*2+0], ah[i], bl[0], bl[2]);
                    mma16816(acc[i][j*2+1], ah[i], bl[1], bl[3]);
                    mma16816(acc[i][j*2+0], al[i], bh[0], bh[2]);
                    mma16816(acc[i][j*2+1], al[i], bh[1], bh[3]);
                }
            }
        }
    }

    const int rbase = row0 + wm * 32 + (lane >> 2);
    const int cbase = wn * 64 + (lane & 3) * 2;
#pragma unroll
    for (int i = 0; i < 2; i++) {
#pragma unroll
        for (int g = 0; g < 8; g++) {
            const int c  = cbase + g * 8;
            const int cg = col0 + c;
            const int r0 = rbase + i * 16;
            float b0 = bias ? bias[cg]     : 0.f;
            float b1 = bias ? bias[cg + 1] : 0.f;
            float v00 = acc[i][g][0] + b0, v01 = acc[i][g][1] + b1;
            float v10 = acc[i][g][2] + b0, v11 = acc[i][g][3] + b1;
            if (mode == 0) {
                *(float2*)(Cf + (size_t)r0 * ldc + cg)     = make_float2(v00, v01);
                *(float2*)(Cf + (size_t)(r0+8) * ldc + cg) = make_float2(v10, v11);
            } else {
                if (mode == 1) {
                    v00 = gelu_exact(v00); v01 = gelu_exact(v01);
                    v10 = gelu_exact(v10); v11 = gelu_exact(v11);
                }
                __nv_bfloat16 h00, l00, h01, l01, h10, l10, h11, l11;
                split_bf16(v00, h00, l00); split_bf16(v01, h01, l01);
                split_bf16(v10, h10, l10); split_bf16(v11, h11, l11);
                *(__nv_bfloat162*)(Chi + (size_t)r0 * ldc + cg)     = __halves2bfloat162(h00, h01);
                *(__nv_bfloat162*)(Chi + (size_t)(r0+8) * ldc + cg) = __halves2bfloat162(h10, h11);
                *(__nv_bfloat162*)(Clo + (size_t)r0 * ldc + cg)     = __halves2bfloat162(l00, l01);
                *(__nv_bfloat162*)(Clo + (size_t)(r0+8) * ldc + cg) = __halves2bfloat162(l10, l11);
            }
        }
    }
}

// ---------------- flash-style tiled attention (fp32, vectorized) -------------
// Heavy q-tiles scheduled first (qt reversed). Inner loops chunked by 4 with
// float4 loads so LDS:FMA drops from ~9:32 to ~3:32 per step.
#define QTILE 128
#define KTILE 64
#define QP 68
#define KP 68
#define VP 68
#define SP 68
#define AQ_OFF 0
#define AK_OFF (AQ_OFF + 128*QP)
#define AV_OFF (AK_OFF + 64*KP)
#define AS_OFF (AV_OFF + 64*VP)
#define AM_OFF (AS_OFF + 128*SP)
#define AL_OFF (AM_OFF + 128)
#define AF_OFF (AL_OFF + 128)
#define AR_OFF (AF_OFF + 128)
#define ATTN_SMEM ((AR_OFF + 256) * 4)

__global__ __launch_bounds__(256)
void attn_flash(const float* __restrict__ qkv,
                __nv_bfloat16* __restrict__ ahi, __nv_bfloat16* __restrict__ alo) {
    extern __shared__ float sm[];
    float* Qs = sm + AQ_OFF;
    float* Kt = sm + AK_OFF;
    float* Vs = sm + AV_OFF;
    float* Ss = sm + AS_OFF;
    float* Mm = sm + AM_OFF;
    float* Ll = sm + AL_OFF;
    float* Fs = sm + AF_OFF;
    float* Red = sm + AR_OFF;

    const int tid = threadIdx.x;
    const int tx = tid & 15, ty = tid >> 4;
    const int bh = blockIdx.y;
    const int b  = bh >> 4;
    const int h  = bh & 15;
    const int qt = (int)gridDim.x - 1 - (int)blockIdx.x;   // heavy tiles first
    const int q0 = qt * QTILE;

#pragma unroll
    for (int i = 0; i < 8; i++) {
        int idx = tid + i * 256;
        int r = idx >> 4, c = idx & 15;
        float4 v = *(const float4*)(qkv + ((size_t)((q0 + r) * BATCH + b)) * D3 + h * DKH + c * 4);
        v.x *= ATT_SCALE; v.y *= ATT_SCALE; v.z *= ATT_SCALE; v.w *= ATT_SCALE;
        *(float4*)(Qs + r * QP + c * 4) = v;
    }
    if (tid < 128) { Mm[tid] = -1e30f; Ll[tid] = 0.f; }

    float acc[8][4];
#pragma unroll
    for (int i = 0; i < 8; i++)
#pragma unroll
        for (int j = 0; j < 4; j++) acc[i][j] = 0.f;

    __syncthreads();

    const int ntiles = qt * 2 + 2;
    const int qred = tid >> 1, hf = tid & 1;

    for (int kt = 0; kt < ntiles; kt++) {
        const int s0 = kt * KTILE;
#pragma unroll
        for (int i = 0; i < 4; i++) {
            int idx = tid + i * 256;
            int r = idx >> 4, c = idx & 15;
            const float* base = qkv + ((size_t)((s0 + r) * BATCH + b)) * D3 + h * DKH + c * 4;
            float4 kv = *(const float4*)(base + D);
            float4 vv = *(const float4*)(base + 2 * D);
            Kt[(c*4+0) * KP + r] = kv.x;
            Kt[(c*4+1) * KP + r] = kv.y;
            Kt[(c*4+2) * KP + r] = kv.z;
            Kt[(c*4+3) * KP + r] = kv.w;
            *(float4*)(Vs + r * VP + c * 4) = vv;
        }
        __syncthreads();

        // ---- scores: chunk d by 4, float4 loads for Q and K ----
        float sreg[8][4];
#pragma unroll
        for (int i = 0; i < 8; i++)
#pragma unroll
            for (int j = 0; j < 4; j++) sreg[i][j] = 0.f;
#pragma unroll 4
        for (int d4 = 0; d4 < 16; d4++) {
            const float4 k0 = *(const float4*)(Kt + (d4*4+0) * KP + tx * 4);
            const float4 k1 = *(const float4*)(Kt + (d4*4+1) * KP + tx * 4);
            const float4 k2 = *(const float4*)(Kt + (d4*4+2) * KP + tx * 4);
            const float4 k3 = *(const float4*)(Kt + (d4*4+3) * KP + tx * 4);
#pragma unroll
            for (int i = 0; i < 8; i++) {
                const float4 q4 = *(const float4*)(Qs + (ty*8+i) * QP + d4 * 4);
                sreg[i][0] += q4.x*k0.x + q4.y*k1.x + q4.z*k2.x + q4.w*k3.x;
                sreg[i][1] += q4.x*k0.y + q4.y*k1.y + q4.z*k2.y + q4.w*k3.y;
                sreg[i][2] += q4.x*k0.z + q4.y*k1.z + q4.z*k2.z + q4.w*k3.z;
                sreg[i][3] += q4.x*k0.w + q4.y*k1.w + q4.z*k2.w + q4.w*k3.w;
            }
        }
#pragma unroll
        for (int i = 0; i < 8; i++) {
            const int qg = q0 + ty * 8 + i;
            float4 o;
            o.x = (s0 + tx*4 + 0 > qg) ? -1e30f : sreg[i][0];
            o.y = (s0 + tx*4 + 1 > qg) ? -1e30f : sreg[i][1];
            o.z = (s0 + tx*4 + 2 > qg) ? -1e30f : sreg[i][2];
            o.w = (s0 + tx*4 + 3 > qg) ? -1e30f : sreg[i][3];
            *(float4*)(Ss + (ty * 8 + i) * SP + tx * 4) = o;
        }
        __syncthreads();

        // ---- row max (vectorized) ----
        {
            const float4* row = (const float4*)(Ss + qred * SP + hf * 32);
            float mx = -1e30f;
#pragma unroll
            for (int j = 0; j < 8; j++) {
                float4 v = row[j];
                mx = fmaxf(mx, fmaxf(fmaxf(v.x, v.y), fmaxf(v.z, v.w)));
            }
            Red[qred * 2 + hf] = mx;
        }
        __syncthreads();
        if (hf == 0) {
            float tm = fmaxf(Red[qred * 2], Red[qred * 2 + 1]);
            float mo = Mm[qred];
            float mn = fmaxf(mo, tm);
            Mm[qred] = mn;
            Fs[qred] = __expf(mo - mn);
        }
        __syncthreads();
        // ---- p = exp(s - m) (vectorized) ----
        {
            const float mq = Mm[qred];
            float4* row = (float4*)(Ss + qred * SP + hf * 32);
            float sum = 0.f;
#pragma unroll
            for (int j = 0; j < 8; j++) {
                float4 v = row[j];
                v.x = __expf(v.x - mq); v.y = __expf(v.y - mq);
                v.z = __expf(v.z - mq); v.w = __expf(v.w - mq);
                row[j] = v;
                sum += v.x + v.y + v.z + v.w;
            }
            Red[qred * 2 + hf] = sum;
        }
        __syncthreads();
        if (hf == 0)
            Ll[qred] = Ll[qred] * Fs[qred] + Red[qred * 2] + Red[qred * 2 + 1];

        // ---- rescale + P@V: chunk s by 4, float4 loads for P and V ----
#pragma unroll
        for (int i = 0; i < 8; i++) {
            const float f = Fs[ty * 8 + i];
#pragma unroll
            for (int j = 0; j < 4; j++) acc[i][j] *= f;
        }
#pragma unroll 4
        for (int s4 = 0; s4 < 16; s4++) {
            const float4 v0 = *(const float4*)(Vs + (s4*4+0) * VP + tx * 4);
            const float4 v1 = *(const float4*)(Vs + (s4*4+1) * VP + tx * 4);
            const float4 v2 = *(const float4*)(Vs + (s4*4+2) * VP + tx * 4);
            const float4 v3 = *(const float4*)(Vs + (s4*4+3) * VP + tx * 4);
#pragma unroll
            for (int i = 0; i < 8; i++) {
                const float4 p4 = *(const float4*)(Ss + (ty*8+i) * SP + s4 * 4);
                acc[i][0] += p4.x*v0.x + p4.y*v1.x + p4.z*v2.x + p4.w*v3.x;
                acc[i][1] += p4.x*v0.y + p4.y*v1.y + p4.z*v2.y + p4.w*v3.y;
                acc[i][2] += p4.x*v0.z + p4.y*v1.z + p4.z*v2.z + p4.w*v3.z;
                acc[i][3] += p4.x*v0.w + p4.y*v1.w + p4.z*v2.w + p4.w*v3.w;
            }
        }
        __syncthreads();
    }

#pragma unroll
    for (int i = 0; i < 8; i++) {
        const int q = ty * 8 + i;
        const float inv = 1.f / Ll[q];
        float v0 = acc[i][0] * inv, v1 = acc[i][1] * inv;
        float v2 = acc[i][2] * inv, v3 = acc[i][3] * inv;
        __nv_bfloat16 h0, l0, h1, l1, h2, l2, h3, l3;
        split_bf16(v0, h0, l0); split_bf16(v1, h1, l1);
        split_bf16(v2, h2, l2); split_bf16(v3, h3, l3);
        size_t base = ((size_t)((q0 + q) * BATCH + b)) * D + h * DKH + tx * 4;
        *(__nv_bfloat162*)(ahi + base)     = __halves2bfloat162(h0, h1);
        *(__nv_bfloat162*)(ahi + base + 2) = __halves2bfloat162(h2, h3);
        *(__nv_bfloat162*)(alo + base)     = __halves2bfloat162(l0, l1);
        *(__nv_bfloat162*)(alo + base + 2) = __halves2bfloat162(l2, l3);
    }
}

// ---------------- fused GRU + LN + splits (one block per token) --------------
__global__ __launch_bounds__(256)
void gru_ln_split(float* __restrict__ px, const float* __restrict__ gate,
                  const float* __restrict__ bg,
                  const float* __restrict__ g, const float* __restrict__ b,
                  __nv_bfloat16* __restrict__ cathi, __nv_bfloat16* __restrict__ catlo,
                  __nv_bfloat16* __restrict__ lnhi, __nv_bfloat16* __restrict__ lnlo,
                  float* __restrict__ outf) {
    const int n = blockIdx.x;
    const int tid = threadIdx.x;
    const float* grow = gate + (size_t)n * D3;
    float vals[4];
    float s = 0.f, sq = 0.f;
#pragma unroll
    for (int k = 0; k < 4; k++) {
        const int j = tid + k * 256;
        float gr = grow[j];
        float gz = grow[D + j];
        float gh = grow[2 * D + j];
        float r = 1.f / (1.f + __expf(-gr));
        float z = 1.f / (1.f + __expf(-(gz - bg[j])));
        float hh = tanhf(gh * r);
        float xv = px[(size_t)n * D + j];
        float v = (1.f - z) * xv + z * hh;
        px[(size_t)n * D + j] = v;
        vals[k] = v;
        __nv_bfloat16 h, l; split_bf16(v, h, l);
        cathi[(size_t)n * D2 + j] = h;
        catlo[(size_t)n * D2 + j] = l;
        s += v; sq += v * v;
    }
    __shared__ float rs[256], rq[256];
    rs[tid] = s; rq[tid] = sq; __syncthreads();
    for (int off = 128; off > 0; off >>= 1) {
        if (tid < off) { rs[tid] += rs[tid + off]; rq[tid] += rq[tid + off]; }
        __syncthreads();
    }
    const float mu  = rs[0] * (1.f / D);
    const float var = rq[0] * (1.f / D) - mu * mu;
    const float inv = rsqrtf(var + 1e-6f);
#pragma unroll
    for (int k = 0; k < 4; k++) {
        const int j = tid + k * 256;
        float y = (vals[k] - mu) * inv * g[j] + b[j];
        if (outf) {
            outf[(size_t)n * D + j] = y;
        } else {
            __nv_bfloat16 h, l; split_bf16(y, h, l);
            lnhi[(size_t)n * D + j] = h;
            lnlo[(size_t)n * D + j] = l;
        }
    }
}

// ---------------- fused GELU+PE + LN + splits (layer-0 entry) ----------------
__global__ __launch_bounds__(256)
void gelu_pe_ln_split(float* __restrict__ px, const float* __restrict__ pe,
                      const float* __restrict__ g, const float* __restrict__ b,
                      __nv_bfloat16* __restrict__ cathi, __nv_bfloat16* __restrict__ catlo,
                      __nv_bfloat16* __restrict__ lnhi, __nv_bfloat16* __restrict__ lnlo) {
    const int n = blockIdx.x;
    const int t = n >> 1;
    const int tid = threadIdx.x;
    float vals[4];
    float s = 0.f, sq = 0.f;
#pragma unroll
    for (int k = 0; k < 4; k++) {
        const int j = tid + k * 256;
        float v = gelu_exact(px[(size_t)n * D + j]) + pe[(size_t)t * D + j];
        px[(size_t)n * D + j] = v;
        vals[k] = v;
        __nv_bfloat16 h, l; split_bf16(v, h, l);
        cathi[(size_t)n * D2 + j] = h;
        catlo[(size_t)n * D2 + j] = l;
        s += v; sq += v * v;
    }
    __shared__ float rs[256], rq[256];
    rs[tid] = s; rq[tid] = sq; __syncthreads();
    for (int off = 128; off > 0; off >>= 1) {
        if (tid < off) { rs[tid] += rs[tid + off]; rq[tid] += rq[tid + off]; }
        __syncthreads();
    }
    const float mu  = rs[0] * (1.f / D);
    const float var = rq[0] * (1.f / D) - mu * mu;
    const float inv = rsqrtf(var + 1e-6f);
#pragma unroll
    for (int k = 0; k < 4; k++) {
        const int j = tid + k * 256;
        float y = (vals[k] - mu) * inv * g[j] + b[j];
        __nv_bfloat16 h, l; split_bf16(y, h, l);
        lnhi[(size_t)n * D + j] = h;
        lnlo[(size_t)n * D + j] = l;
    }
}

// ---------------- f32 -> hi/lo bf16 split (weights + input) ----------------
__global__ void cvt_split4(const float4* __restrict__ x,
                           __nv_bfloat162* __restrict__ hi, __nv_bfloat162* __restrict__ lo,
                           int n4) {
    int i = blockIdx.x * blockDim.x + threadIdx.x;
    if (i >= n4) return;
    float4 v = x[i];
    __nv_bfloat16 h0, l0, h1, l1, h2, l2, h3, l3;
    split_bf16(v.x, h0, l0); split_bf16(v.y, h1, l1);
    split_bf16(v.z, h2, l2); split_bf16(v.w, h3, l3);
    hi[2*i]   = __halves2bfloat162(h0, h1);
    hi[2*i+1] = __halves2bfloat162(h2, h3);
    lo[2*i]   = __halves2bfloat162(l0, l1);
    lo[2*i+1] = __halves2bfloat162(l2, l3);
}

// ---------------- driver ----------------
extern "C" void kernel_launch(void* const* d_in, const int* in_sizes, int n_in,
                              void* d_out, int out_size) {
    const float* x_in  = (const float*)d_in[0];
    const float* pe    = (const float*)d_in[1];
    const float* in_w  = (const float*)d_in[2];
    const float* in_b  = (const float*)d_in[3];
    const float* qkv_w = (const float*)d_in[4];
    const float* out_w = (const float*)d_in[5];
    const float* out_b = (const float*)d_in[6];
    const float* ln1_g = (const float*)d_in[7];
    const float* ln1_b = (const float*)d_in[8];
    const float* ln2_g = (const float*)d_in[9];
    const float* ln2_b = (const float*)d_in[10];
    const float* ff_w1 = (const float*)d_in[11];
    const float* ff_b1 = (const float*)d_in[12];
    const float* ff_w2 = (const float*)d_in[13];
    const float* ff_b2 = (const float*)d_in[14];
    const float* g1_w  = (const float*)d_in[15];
    const float* g1_bg = (const float*)d_in[16];
    const float* g2_w  = (const float*)d_in[17];
    const float* g2_bg = (const float*)d_in[18];
    const float* on_g  = (const float*)d_in[19];
    const float* on_b  = (const float*)d_in[20];

    float *px, *pqkv, *pgate;
    __nv_bfloat16 *chi, *clo, *lhi, *llo, *phi, *plo, *fhi, *flo, *xhi, *xlo;
    __nv_bfloat16 *w_in_h, *w_in_l, *w_qkv_h, *w_qkv_l, *w_out_h, *w_out_l;
    __nv_bfloat16 *w_f1_h, *w_f1_l, *w_f2_h, *w_f2_l, *w_g1_h, *w_g1_l, *w_g2_h, *w_g2_l;
    cudaGetSymbolAddress((void**)&px,    g_x);
    cudaGetSymbolAddress((void**)&pqkv,  g_qkv);
    cudaGetSymbolAddress((void**)&pgate, g_gate);
    cudaGetSymbolAddress((void**)&chi,   g_chi);  cudaGetSymbolAddress((void**)&clo,   g_clo);
    cudaGetSymbolAddress((void**)&lhi,   g_lhi);  cudaGetSymbolAddress((void**)&llo,   g_llo);
    cudaGetSymbolAddress((void**)&phi,   g_phi);  cudaGetSymbolAddress((void**)&plo,   g_plo);
    cudaGetSymbolAddress((void**)&fhi,   g_fhi);  cudaGetSymbolAddress((void**)&flo,   g_flo);
    cudaGetSymbolAddress((void**)&xhi,   g_xhi);  cudaGetSymbolAddress((void**)&xlo,   g_xlo);
    cudaGetSymbolAddress((void**)&w_in_h,  wb_in_hi);  cudaGetSymbolAddress((void**)&w_in_l,  wb_in_lo);
    cudaGetSymbolAddress((void**)&w_qkv_h, wb_qkv_hi); cudaGetSymbolAddress((void**)&w_qkv_l, wb_qkv_lo);
    cudaGetSymbolAddress((void**)&w_out_h, wb_out_hi); cudaGetSymbolAddress((void**)&w_out_l, wb_out_lo);
    cudaGetSymbolAddress((void**)&w_f1_h,  wb_f1_hi);  cudaGetSymbolAddress((void**)&w_f1_l,  wb_f1_lo);
    cudaGetSymbolAddress((void**)&w_f2_h,  wb_f2_hi);  cudaGetSymbolAddress((void**)&w_f2_l,  wb_f2_lo);
    cudaGetSymbolAddress((void**)&w_g1_h,  wb_g1_hi);  cudaGetSymbolAddress((void**)&w_g1_l,  wb_g1_lo);
    cudaGetSymbolAddress((void**)&w_g2_h,  wb_g2_hi);  cudaGetSymbolAddress((void**)&w_g2_l,  wb_g2_lo);

    cudaFuncSetAttribute(gemm_mma, cudaFuncAttributeMaxDynamicSharedMemorySize, SMEM_BYTES);
    cudaFuncSetAttribute(attn_flash, cudaFuncAttributeMaxDynamicSharedMemorySize, ATTN_SMEM);

    const int EW = 256;
    auto cvtgrid = [](int n) { return (n / 4 + 255) / 256; };

    // ---- weight + input hi/lo splits ----
    cvt_split4<<<cvtgrid(D*D),        EW>>>((const float4*)in_w,  (__nv_bfloat162*)w_in_h,  (__nv_bfloat162*)w_in_l,  D*D/4);
    cvt_split4<<<cvtgrid(LNUM*D3*D),  EW>>>((const float4*)qkv_w, (__nv_bfloat162*)w_qkv_h, (__nv_bfloat162*)w_qkv_l, LNUM*D3*D/4);
    cvt_split4<<<cvtgrid(LNUM*D*D),   EW>>>((const float4*)out_w, (__nv_bfloat162*)w_out_h, (__nv_bfloat162*)w_out_l, LNUM*D*D/4);
    cvt_split4<<<cvtgrid(LNUM*FFD*D), EW>>>((const float4*)ff_w1, (__nv_bfloat162*)w_f1_h,  (__nv_bfloat162*)w_f1_l,  LNUM*FFD*D/4);
    cvt_split4<<<cvtgrid(LNUM*D*FFD), EW>>>((const float4*)ff_w2, (__nv_bfloat162*)w_f2_h,  (__nv_bfloat162*)w_f2_l,  LNUM*D*FFD/4);
    cvt_split4<<<cvtgrid(LNUM*D3*D2), EW>>>((const float4*)g1_w,  (__nv_bfloat162*)w_g1_h,  (__nv_bfloat162*)w_g1_l,  LNUM*D3*D2/4);
    cvt_split4<<<cvtgrid(LNUM*D3*D2), EW>>>((const float4*)g2_w,  (__nv_bfloat162*)w_g2_h,  (__nv_bfloat162*)w_g2_l,  LNUM*D3*D2/4);
    cvt_split4<<<cvtgrid(NTOK*D),     EW>>>((const float4*)x_in,  (__nv_bfloat162*)xhi,     (__nv_bfloat162*)xlo,     NTOK*D/4);

    dim3 gD  (D/128,   NTOK/128);
    dim3 gD3 (D3/128,  NTOK/128);
    dim3 gFF (FFD/128, NTOK/128);

    // ---- input projection, then fused gelu+pe+LN1+splits ----
    gemm_mma<<<gD, 256, SMEM_BYTES>>>(xhi, xlo, D, w_in_h, w_in_l, in_b, px, 0, 0, D, D, 0);
    gelu_pe_ln_split<<<NTOK, 256>>>(px, pe, ln1_g, ln1_b, chi, clo, lhi, llo);

    for (int l = 0; l < LNUM; l++) {
        const __nv_bfloat16* qwh = w_qkv_h + (size_t)l*D3*D;  const __nv_bfloat16* qwl = w_qkv_l + (size_t)l*D3*D;
        const __nv_bfloat16* owh = w_out_h + (size_t)l*D*D;   const __nv_bfloat16* owl = w_out_l + (size_t)l*D*D;
        const __nv_bfloat16* f1h = w_f1_h  + (size_t)l*FFD*D; const __nv_bfloat16* f1l = w_f1_l  + (size_t)l*FFD*D;
        const __nv_bfloat16* f2h = w_f2_h  + (size_t)l*D*FFD; const __nv_bfloat16* f2l = w_f2_l  + (size_t)l*D*FFD;
        const __nv_bfloat16* g1h = w_g1_h  + (size_t)l*D3*D2; const __nv_bfloat16* g1l = w_g1_l  + (size_t)l*D3*D2;
        const __nv_bfloat16* g2h = w_g2_h  + (size_t)l*D3*D2; const __nv_bfloat16* g2l = w_g2_l  + (size_t)l*D3*D2;
        const float* ob  = out_b + (size_t)l*D;
        const float* l2g = ln2_g + (size_t)l*D;  const float* l2b = ln2_b + (size_t)l*D;
        const float* fb1 = ff_b1 + (size_t)l*FFD;
        const float* fb2 = ff_b2 + (size_t)l*D;
        const float* gb1 = g1_bg + (size_t)l*D;
        const float* gb2 = g2_bg + (size_t)l*D;
        const float* ng = (l + 1 < LNUM) ? ln1_g + (size_t)(l+1)*D : on_g;
        const float* nb = (l + 1 < LNUM) ? ln1_b + (size_t)(l+1)*D : on_b;
        float* fout = (l + 1 < LNUM) ? nullptr : (float*)d_out;

        // attention block
        gemm_mma<<<gD3, 256, SMEM_BYTES>>>(lhi, llo, D, qwh, qwl, nullptr, pqkv, 0, 0, D3, D, 0);
        attn_flash<<<dim3(TT/QTILE, BATCH*H), 256, ATTN_SMEM>>>(pqkv, phi, plo);
        gemm_mma<<<gD, 256, SMEM_BYTES>>>(phi, plo, D, owh, owl, ob, 0, chi + D, clo + D, D2, D, 2);
        gemm_mma<<<gD3, 256, SMEM_BYTES>>>(chi, clo, D2, g1h, g1l, nullptr, pgate, 0, 0, D3, D2, 0);
        gru_ln_split<<<NTOK, 256>>>(px, pgate, gb1, l2g, l2b, chi, clo, lhi, llo, nullptr);

        // feed-forward block
        gemm_mma<<<gFF, 256, SMEM_BYTES>>>(lhi, llo, D, f1h, f1l, fb1, 0, fhi, flo, FFD, D, 1);
        gemm_mma<<<gD, 256, SMEM_BYTES>>>(fhi, flo, FFD, f2h, f2l, fb2, 0, chi + D, clo + D, D2, FFD, 2);
        gemm_mma<<<gD3, 256, SMEM_BYTES>>>(chi, clo, D2, g2h, g2l, nullptr, pgate, 0, 0, D3, D2, 0);
        gru_ln_split<<<NTOK, 256>>>(px, pgate, gb2, ng, nb, chi, clo, lhi, llo, fout);
    }
}

// round 8
// speedup vs baseline: 1.0221x; 1.0140x over previous
#include <cuda_runtime.h>
#include <cuda_bf16.h>
#include <math.h>
#include <stdint.h>

// ---------------- problem constants ----------------
#define LNUM  6
#define D     1024
#define H     16
#define DKH   64
#define FFD   4096
#define TT    1024
#define BATCH 2
#define NTOK  2048
#define D3    3072
#define D2    2048
#define ATT_SCALE 0.125f

#define SWZ(o) ((o) ^ (((o) >> 3) & 0x70))

// ---------------- scratch (device globals; no allocs allowed) ----------------
__device__ float g_x   [NTOK*D];     // residual stream (f32)
__device__ float g_qkv [NTOK*D3];
__device__ float g_gate[NTOK*D3];
__device__ __nv_bfloat16 g_chi[NTOK*D2],  g_clo[NTOK*D2];   // concat [x,y] hi/lo
__device__ __nv_bfloat16 g_lhi[NTOK*D],   g_llo[NTOK*D];    // LN output hi/lo
__device__ __nv_bfloat16 g_phi[NTOK*D],   g_plo[NTOK*D];    // attn output hi/lo
__device__ __nv_bfloat16 g_fhi[NTOK*FFD], g_flo[NTOK*FFD];  // FF hidden hi/lo
__device__ __nv_bfloat16 g_xhi[NTOK*D],   g_xlo[NTOK*D];    // input x split
__device__ __nv_bfloat16 wb_in_hi [D*D],        wb_in_lo [D*D];
__device__ __nv_bfloat16 wb_qkv_hi[LNUM*D3*D],  wb_qkv_lo[LNUM*D3*D];
__device__ __nv_bfloat16 wb_out_hi[LNUM*D*D],   wb_out_lo[LNUM*D*D];
__device__ __nv_bfloat16 wb_f1_hi [LNUM*FFD*D], wb_f1_lo [LNUM*FFD*D];
__device__ __nv_bfloat16 wb_f2_hi [LNUM*D*FFD], wb_f2_lo [LNUM*D*FFD];
__device__ __nv_bfloat16 wb_g1_hi [LNUM*D3*D2], wb_g1_lo [LNUM*D3*D2];
__device__ __nv_bfloat16 wb_g2_hi [LNUM*D3*D2], wb_g2_lo [LNUM*D3*D2];

// ---------------- PTX helpers (portable: sm_80-level) ----------------
__device__ __forceinline__ uint32_t smem_u32(const void* p) {
    uint32_t a;
    asm("{ .reg .u64 t; cvta.to.shared.u64 t, %1; cvt.u32.u64 %0, t; }" : "=r"(a) : "l"(p));
    return a;
}
__device__ __forceinline__ void cp16(uint32_t d, const void* g) {
    asm volatile("cp.async.cg.shared.global [%0], [%1], 16;" :: "r"(d), "l"(g));
}
__device__ __forceinline__ void ldm_x4(uint32_t* f, uint32_t addr) {
    asm volatile("ldmatrix.sync.aligned.m8n8.x4.shared.b16 {%0,%1,%2,%3}, [%4];"
                 : "=r"(f[0]), "=r"(f[1]), "=r"(f[2]), "=r"(f[3]) : "r"(addr));
}
__device__ __forceinline__ void mma16816(float* c, const uint32_t* a, uint32_t b0, uint32_t b1) {
    asm volatile(
        "mma.sync.aligned.m16n8k16.row.col.f32.bf16.bf16.f32 "
        "{%0,%1,%2,%3}, {%4,%5,%6,%7}, {%8,%9}, {%0,%1,%2,%3};"
        : "+f"(c[0]), "+f"(c[1]), "+f"(c[2]), "+f"(c[3])
        : "r"(a[0]), "r"(a[1]), "r"(a[2]), "r"(a[3]), "r"(b0), "r"(b1));
}
__device__ __forceinline__ float gelu_exact(float v) { return v * normcdff(v); }
__device__ __forceinline__ void split_bf16(float v, __nv_bfloat16& h, __nv_bfloat16& l) {
    h = __float2bfloat16(v);
    l = __float2bfloat16(v - __bfloat162float(h));
}

// ---------------- bf16 hi/lo split GEMM (persistent CTAs, cross-tile pipe) ---
// C[NTOK,ncols] = A[NTOK,K] @ W[ncols,K]^T (3-term hi/lo accumulation)
// Persistent grid: each CTA loops over tiles; the 2-stage cp.async ring runs
// continuously across tile boundaries so the epilogue overlaps the next
// tile's loads.
// mode 0: Cf = result (+bias). mode 1: gelu -> hi/lo bf16. mode 2: -> hi/lo.
#define STAGE_B 65536
#define SMEM_BYTES (2*STAGE_B)

__global__ __launch_bounds__(256)
void gemm_mma(const __nv_bfloat16* __restrict__ Ahi, const __nv_bfloat16* __restrict__ Alo,
              int lda,
              const __nv_bfloat16* __restrict__ Whi, const __nv_bfloat16* __restrict__ Wlo,
              const float* __restrict__ bias,
              float* __restrict__ Cf,
              __nv_bfloat16* __restrict__ Chi, __nv_bfloat16* __restrict__ Clo,
              int ldc, int K, int mode, int gx, int ntiles)
{
    extern __shared__ char smem[];
    const uint32_t sb = smem_u32(smem);
    const int tid  = threadIdx.x;
    const int wid  = tid >> 5;
    const int lane = tid & 31;
    const int wm   = wid >> 1;
    const int wn   = wid & 1;

    const int lr   = lane & 15;
    const int koff = (lane >> 4) << 4;
    uint32_t roffA[2], rxA[2], roffB[4], rxB[4];
#pragma unroll
    for (int i = 0; i < 2; i++) {
        int r = wm * 32 + i * 16 + lr;
        roffA[i] = r * 128; rxA[i] = (r & 7) << 4;
    }
#pragma unroll
    for (int j = 0; j < 4; j++) {
        int r = wn * 64 + j * 16 + lr;
        roffB[j] = r * 128; rxB[j] = (r & 7) << 4;
    }

    const int nch = K / 64;
    const int ldr = tid >> 3, ldc4 = tid & 7;

    // issue chunk cc of tile tt into stage
    auto issue = [&](int tt, int cc, int stage) {
        const int r0 = (tt / gx) * 128;
        const int c0 = (tt % gx) * 128;
        const int kbase = cc * 64;
        const uint32_t st = sb + stage * STAGE_B;
#pragma unroll
        for (int i = 0; i < 4; i++) {
            int r = ldr + i * 32;
            uint32_t off = SWZ((uint32_t)(r * 128 + ldc4 * 16));
            size_t sa = (size_t)(r0 + r) * lda + kbase + ldc4 * 8;
            size_t sw = (size_t)(c0 + r) * K   + kbase + ldc4 * 8;
            cp16(st +         off, Ahi + sa);
            cp16(st + 16384 + off, Alo + sa);
            cp16(st + 32768 + off, Whi + sw);
            cp16(st + 49152 + off, Wlo + sw);
        }
        asm volatile("cp.async.commit_group;");
    };

    const int grid = (int)gridDim.x;
    int cur_stage = 0;
    issue(blockIdx.x, 0, 0);

    for (int t = blockIdx.x; t < ntiles; t += grid) {
        const int row0 = (t / gx) * 128;
        const int col0 = (t % gx) * 128;

        float acc[2][8][4];
#pragma unroll
        for (int i = 0; i < 2; i++)
#pragma unroll
            for (int g = 0; g < 8; g++)
#pragma unroll
                for (int q = 0; q < 4; q++) acc[i][g][q] = 0.f;

        for (int cc = 0; cc < nch; cc++) {
            asm volatile("cp.async.wait_group 0;");
            __syncthreads();
            const int nxt = cur_stage ^ 1;
            if (cc + 1 < nch)              issue(t, cc + 1, nxt);
            else if (t + grid < ntiles)    issue(t + grid, 0, nxt);

            const uint32_t AH = sb + cur_stage * STAGE_B;
            const uint32_t AL = AH + 16384;
            const uint32_t WHs = AH + 32768;
            const uint32_t WLs = AH + 49152;
#pragma unroll
            for (int ks = 0; ks < 4; ks++) {
                const uint32_t kb = ks * 32 + koff;
                uint32_t ah[2][4], al[2][4];
#pragma unroll
                for (int i = 0; i < 2; i++) {
                    ldm_x4(ah[i], AH + roffA[i] + (kb ^ rxA[i]));
                    ldm_x4(al[i], AL + roffA[i] + (kb ^ rxA[i]));
                }
#pragma unroll
                for (int j = 0; j < 4; j++) {
                    uint32_t bh[4], bl[4];
                    ldm_x4(bh, WHs + roffB[j] + (kb ^ rxB[j]));
                    ldm_x4(bl, WLs + roffB[j] + (kb ^ rxB[j]));
#pragma unroll
                    for (int i = 0; i < 2; i++) {
                        mma16816(acc[i][j*2+0], ah[i], bh[0], bh[2]);
                        mma16816(acc[i][j*2+1], ah[i], bh[1], bh[3]);
                        mma16816(acc[i][j*2+0], ah[i], bl[0], bl[2]);
                        mma16816(acc[i][j*2+1], ah[i], bl[1], bl[3]);
                        mma16816(acc[i][j*2+0], al[i], bh[0], bh[2]);
                        mma16816(acc[i][j*2+1], al[i], bh[1], bh[3]);
                    }
                }
            }
            cur_stage ^= 1;
        }

        // ---- epilogue (overlaps next tile's chunk-0 cp.async) ----
        const int rbase = row0 + wm * 32 + (lane >> 2);
        const int cbase = wn * 64 + (lane & 3) * 2;
#pragma unroll
        for (int i = 0; i < 2; i++) {
#pragma unroll
            for (int g = 0; g < 8; g++) {
                const int c  = cbase + g * 8;
                const int cg = col0 + c;
                const int r0 = rbase + i * 16;
                float b0 = bias ? bias[cg]     : 0.f;
                float b1 = bias ? bias[cg + 1] : 0.f;
                float v00 = acc[i][g][0] + b0, v01 = acc[i][g][1] + b1;
                float v10 = acc[i][g][2] + b0, v11 = acc[i][g][3] + b1;
                if (mode == 0) {
                    *(float2*)(Cf + (size_t)r0 * ldc + cg)     = make_float2(v00, v01);
                    *(float2*)(Cf + (size_t)(r0+8) * ldc + cg) = make_float2(v10, v11);
                } else {
                    if (mode == 1) {
                        v00 = gelu_exact(v00); v01 = gelu_exact(v01);
                        v10 = gelu_exact(v10); v11 = gelu_exact(v11);
                    }
                    __nv_bfloat16 h00, l00, h01, l01, h10, l10, h11, l11;
                    split_bf16(v00, h00, l00); split_bf16(v01, h01, l01);
                    split_bf16(v10, h10, l10); split_bf16(v11, h11, l11);
                    *(__nv_bfloat162*)(Chi + (size_t)r0 * ldc + cg)     = __halves2bfloat162(h00, h01);
                    *(__nv_bfloat162*)(Chi + (size_t)(r0+8) * ldc + cg) = __halves2bfloat162(h10, h11);
                    *(__nv_bfloat162*)(Clo + (size_t)r0 * ldc + cg)     = __halves2bfloat162(l00, l01);
                    *(__nv_bfloat162*)(Clo + (size_t)(r0+8) * ldc + cg) = __halves2bfloat162(l10, l11);
                }
            }
        }
    }
}

// ---------------- flash-style tiled attention (fp32, R5 version) -------------
#define QTILE 128
#define KTILE 64
#define QP 68
#define KP 68
#define VP 68
#define SP 68
#define AQ_OFF 0
#define AK_OFF (AQ_OFF + 128*QP)
#define AV_OFF (AK_OFF + 64*KP)
#define AS_OFF (AV_OFF + 64*VP)
#define AM_OFF (AS_OFF + 128*SP)
#define AL_OFF (AM_OFF + 128)
#define AF_OFF (AL_OFF + 128)
#define AR_OFF (AF_OFF + 128)
#define ATTN_SMEM ((AR_OFF + 256) * 4)

__global__ __launch_bounds__(256)
void attn_flash(const float* __restrict__ qkv,
                __nv_bfloat16* __restrict__ ahi, __nv_bfloat16* __restrict__ alo) {
    extern __shared__ float sm[];
    float* Qs = sm + AQ_OFF;
    float* Kt = sm + AK_OFF;
    float* Vs = sm + AV_OFF;
    float* Ss = sm + AS_OFF;
    float* Mm = sm + AM_OFF;
    float* Ll = sm + AL_OFF;
    float* Fs = sm + AF_OFF;
    float* Red = sm + AR_OFF;

    const int tid = threadIdx.x;
    const int tx = tid & 15, ty = tid >> 4;
    const int bh = blockIdx.y;
    const int b  = bh >> 4;
    const int h  = bh & 15;
    const int q0 = blockIdx.x * QTILE;

#pragma unroll
    for (int i = 0; i < 8; i++) {
        int idx = tid + i * 256;
        int r = idx >> 4, c = idx & 15;
        float4 v = *(const float4*)(qkv + ((size_t)((q0 + r) * BATCH + b)) * D3 + h * DKH + c * 4);
        v.x *= ATT_SCALE; v.y *= ATT_SCALE; v.z *= ATT_SCALE; v.w *= ATT_SCALE;
        *(float4*)(Qs + r * QP + c * 4) = v;
    }
    if (tid < 128) { Mm[tid] = -1e30f; Ll[tid] = 0.f; }

    float acc[8][4];
#pragma unroll
    for (int i = 0; i < 8; i++)
#pragma unroll
        for (int j = 0; j < 4; j++) acc[i][j] = 0.f;

    __syncthreads();

    const int ntiles = blockIdx.x * 2 + 2;
    const int qred = tid >> 1, hf = tid & 1;

    for (int kt = 0; kt < ntiles; kt++) {
        const int s0 = kt * KTILE;
#pragma unroll
        for (int i = 0; i < 4; i++) {
            int idx = tid + i * 256;
            int r = idx >> 4, c = idx & 15;
            const float* base = qkv + ((size_t)((s0 + r) * BATCH + b)) * D3 + h * DKH + c * 4;
            float4 kv = *(const float4*)(base + D);
            float4 vv = *(const float4*)(base + 2 * D);
            Kt[(c*4+0) * KP + r] = kv.x;
            Kt[(c*4+1) * KP + r] = kv.y;
            Kt[(c*4+2) * KP + r] = kv.z;
            Kt[(c*4+3) * KP + r] = kv.w;
            *(float4*)(Vs + r * VP + c * 4) = vv;
        }
        __syncthreads();

        float sreg[8][4];
#pragma unroll
        for (int i = 0; i < 8; i++)
#pragma unroll
            for (int j = 0; j < 4; j++) sreg[i][j] = 0.f;
#pragma unroll 8
        for (int d = 0; d < 64; d++) {
            const float4 kq = *(const float4*)(Kt + d * KP + tx * 4);
#pragma unroll
            for (int i = 0; i < 8; i++) {
                float qv = Qs[(ty * 8 + i) * QP + d];
                sreg[i][0] += qv * kq.x;
                sreg[i][1] += qv * kq.y;
                sreg[i][2] += qv * kq.z;
                sreg[i][3] += qv * kq.w;
            }
        }
#pragma unroll
        for (int i = 0; i < 8; i++) {
            const int qg = q0 + ty * 8 + i;
            float4 o;
            o.x = (s0 + tx*4 + 0 > qg) ? -1e30f : sreg[i][0];
            o.y = (s0 + tx*4 + 1 > qg) ? -1e30f : sreg[i][1];
            o.z = (s0 + tx*4 + 2 > qg) ? -1e30f : sreg[i][2];
            o.w = (s0 + tx*4 + 3 > qg) ? -1e30f : sreg[i][3];
            *(float4*)(Ss + (ty * 8 + i) * SP + tx * 4) = o;
        }
        __syncthreads();

        {
            float mx = -1e30f;
            const float* row = Ss + qred * SP + hf * 32;
#pragma unroll 8
            for (int j = 0; j < 32; j++) mx = fmaxf(mx, row[j]);
            Red[qred * 2 + hf] = mx;
        }
        __syncthreads();
        if (hf == 0) {
            float tm = fmaxf(Red[qred * 2], Red[qred * 2 + 1]);
            float mo = Mm[qred];
            float mn = fmaxf(mo, tm);
            Mm[qred] = mn;
            Fs[qred] = __expf(mo - mn);
        }
        __syncthreads();
        {
            const float mq = Mm[qred];
            float* row = Ss + qred * SP + hf * 32;
            float sum = 0.f;
#pragma unroll 8
            for (int j = 0; j < 32; j++) {
                float e = __expf(row[j] - mq);
                row[j] = e; sum += e;
            }
            Red[qred * 2 + hf] = sum;
        }
        __syncthreads();
        if (hf == 0)
            Ll[qred] = Ll[qred] * Fs[qred] + Red[qred * 2] + Red[qred * 2 + 1];

#pragma unroll
        for (int i = 0; i < 8; i++) {
            const float f = Fs[ty * 8 + i];
#pragma unroll
            for (int j = 0; j < 4; j++) acc[i][j] *= f;
        }
#pragma unroll 4
        for (int s = 0; s < 64; s++) {
            const float4 v4 = *(const float4*)(Vs + s * VP + tx * 4);
#pragma unroll
            for (int i = 0; i < 8; i++) {
                const float p = Ss[(ty * 8 + i) * SP + s];
                acc[i][0] += p * v4.x;
                acc[i][1] += p * v4.y;
                acc[i][2] += p * v4.z;
                acc[i][3] += p * v4.w;
            }
        }
        __syncthreads();
    }

#pragma unroll
    for (int i = 0; i < 8; i++) {
        const int q = ty * 8 + i;
        const float inv = 1.f / Ll[q];
        float v0 = acc[i][0] * inv, v1 = acc[i][1] * inv;
        float v2 = acc[i][2] * inv, v3 = acc[i][3] * inv;
        __nv_bfloat16 h0, l0, h1, l1, h2, l2, h3, l3;
        split_bf16(v0, h0, l0); split_bf16(v1, h1, l1);
        split_bf16(v2, h2, l2); split_bf16(v3, h3, l3);
        size_t base = ((size_t)((q0 + q) * BATCH + b)) * D + h * DKH + tx * 4;
        *(__nv_bfloat162*)(ahi + base)     = __halves2bfloat162(h0, h1);
        *(__nv_bfloat162*)(ahi + base + 2) = __halves2bfloat162(h2, h3);
        *(__nv_bfloat162*)(alo + base)     = __halves2bfloat162(l0, l1);
        *(__nv_bfloat162*)(alo + base + 2) = __halves2bfloat162(l2, l3);
    }
}

// ---------------- fused GRU + LN + splits (one block per token) --------------
__global__ __launch_bounds__(256)
void gru_ln_split(float* __restrict__ px, const float* __restrict__ gate,
                  const float* __restrict__ bg,
                  const float* __restrict__ g, const float* __restrict__ b,
                  __nv_bfloat16* __restrict__ cathi, __nv_bfloat16* __restrict__ catlo,
                  __nv_bfloat16* __restrict__ lnhi, __nv_bfloat16* __restrict__ lnlo,
                  float* __restrict__ outf) {
    const int n = blockIdx.x;
    const int tid = threadIdx.x;
    const float* grow = gate + (size_t)n * D3;
    float vals[4];
    float s = 0.f, sq = 0.f;
#pragma unroll
    for (int k = 0; k < 4; k++) {
        const int j = tid + k * 256;
        float gr = grow[j];
        float gz = grow[D + j];
        float gh = grow[2 * D + j];
        float r = 1.f / (1.f + __expf(-gr));
        float z = 1.f / (1.f + __expf(-(gz - bg[j])));
        float hh = tanhf(gh * r);
        float xv = px[(size_t)n * D + j];
        float v = (1.f - z) * xv + z * hh;
        px[(size_t)n * D + j] = v;
        vals[k] = v;
        __nv_bfloat16 h, l; split_bf16(v, h, l);
        cathi[(size_t)n * D2 + j] = h;
        catlo[(size_t)n * D2 + j] = l;
        s += v; sq += v * v;
    }
    __shared__ float rs[256], rq[256];
    rs[tid] = s; rq[tid] = sq; __syncthreads();
    for (int off = 128; off > 0; off >>= 1) {
        if (tid < off) { rs[tid] += rs[tid + off]; rq[tid] += rq[tid + off]; }
        __syncthreads();
    }
    const float mu  = rs[0] * (1.f / D);
    const float var = rq[0] * (1.f / D) - mu * mu;
    const float inv = rsqrtf(var + 1e-6f);
#pragma unroll
    for (int k = 0; k < 4; k++) {
        const int j = tid + k * 256;
        float y = (vals[k] - mu) * inv * g[j] + b[j];
        if (outf) {
            outf[(size_t)n * D + j] = y;
        } else {
            __nv_bfloat16 h, l; split_bf16(y, h, l);
            lnhi[(size_t)n * D + j] = h;
            lnlo[(size_t)n * D + j] = l;
        }
    }
}

// ---------------- fused GELU+PE + LN + splits (layer-0 entry) ----------------
__global__ __launch_bounds__(256)
void gelu_pe_ln_split(float* __restrict__ px, const float* __restrict__ pe,
                      const float* __restrict__ g, const float* __restrict__ b,
                      __nv_bfloat16* __restrict__ cathi, __nv_bfloat16* __restrict__ catlo,
                      __nv_bfloat16* __restrict__ lnhi, __nv_bfloat16* __restrict__ lnlo) {
    const int n = blockIdx.x;
    const int t = n >> 1;
    const int tid = threadIdx.x;
    float vals[4];
    float s = 0.f, sq = 0.f;
#pragma unroll
    for (int k = 0; k < 4; k++) {
        const int j = tid + k * 256;
        float v = gelu_exact(px[(size_t)n * D + j]) + pe[(size_t)t * D + j];
        px[(size_t)n * D + j] = v;
        vals[k] = v;
        __nv_bfloat16 h, l; split_bf16(v, h, l);
        cathi[(size_t)n * D2 + j] = h;
        catlo[(size_t)n * D2 + j] = l;
        s += v; sq += v * v;
    }
    __shared__ float rs[256], rq[256];
    rs[tid] = s; rq[tid] = sq; __syncthreads();
    for (int off = 128; off > 0; off >>= 1) {
        if (tid < off) { rs[tid] += rs[tid + off]; rq[tid] += rq[tid + off]; }
        __syncthreads();
    }
    const float mu  = rs[0] * (1.f / D);
    const float var = rq[0] * (1.f / D) - mu * mu;
    const float inv = rsqrtf(var + 1e-6f);
#pragma unroll
    for (int k = 0; k < 4; k++) {
        const int j = tid + k * 256;
        float y = (vals[k] - mu) * inv * g[j] + b[j];
        __nv_bfloat16 h, l; split_bf16(y, h, l);
        lnhi[(size_t)n * D + j] = h;
        lnlo[(size_t)n * D + j] = l;
    }
}

// ---------------- f32 -> hi/lo bf16 split (weights + input) ----------------
__global__ void cvt_split4(const float4* __restrict__ x,
                           __nv_bfloat162* __restrict__ hi, __nv_bfloat162* __restrict__ lo,
                           int n4) {
    int i = blockIdx.x * blockDim.x + threadIdx.x;
    if (i >= n4) return;
    float4 v = x[i];
    __nv_bfloat16 h0, l0, h1, l1, h2, l2, h3, l3;
    split_bf16(v.x, h0, l0); split_bf16(v.y, h1, l1);
    split_bf16(v.z, h2, l2); split_bf16(v.w, h3, l3);
    hi[2*i]   = __halves2bfloat162(h0, h1);
    hi[2*i+1] = __halves2bfloat162(h2, h3);
    lo[2*i]   = __halves2bfloat162(l0, l1);
    lo[2*i+1] = __halves2bfloat162(l2, l3);
}

// ---------------- driver ----------------
extern "C" void kernel_launch(void* const* d_in, const int* in_sizes, int n_in,
                              void* d_out, int out_size) {
    const float* x_in  = (const float*)d_in[0];
    const float* pe    = (const float*)d_in[1];
    const float* in_w  = (const float*)d_in[2];
    const float* in_b  = (const float*)d_in[3];
    const float* qkv_w = (const float*)d_in[4];
    const float* out_w = (const float*)d_in[5];
    const float* out_b = (const float*)d_in[6];
    const float* ln1_g = (const float*)d_in[7];
    const float* ln1_b = (const float*)d_in[8];
    const float* ln2_g = (const float*)d_in[9];
    const float* ln2_b = (const float*)d_in[10];
    const float* ff_w1 = (const float*)d_in[11];
    const float* ff_b1 = (const float*)d_in[12];
    const float* ff_w2 = (const float*)d_in[13];
    const float* ff_b2 = (const float*)d_in[14];
    const float* g1_w  = (const float*)d_in[15];
    const float* g1_bg = (const float*)d_in[16];
    const float* g2_w  = (const float*)d_in[17];
    const float* g2_bg = (const float*)d_in[18];
    const float* on_g  = (const float*)d_in[19];
    const float* on_b  = (const float*)d_in[20];

    float *px, *pqkv, *pgate;
    __nv_bfloat16 *chi, *clo, *lhi, *llo, *phi, *plo, *fhi, *flo, *xhi, *xlo;
    __nv_bfloat16 *w_in_h, *w_in_l, *w_qkv_h, *w_qkv_l, *w_out_h, *w_out_l;
    __nv_bfloat16 *w_f1_h, *w_f1_l, *w_f2_h, *w_f2_l, *w_g1_h, *w_g1_l, *w_g2_h, *w_g2_l;
    cudaGetSymbolAddress((void**)&px,    g_x);
    cudaGetSymbolAddress((void**)&pqkv,  g_qkv);
    cudaGetSymbolAddress((void**)&pgate, g_gate);
    cudaGetSymbolAddress((void**)&chi,   g_chi);  cudaGetSymbolAddress((void**)&clo,   g_clo);
    cudaGetSymbolAddress((void**)&lhi,   g_lhi);  cudaGetSymbolAddress((void**)&llo,   g_llo);
    cudaGetSymbolAddress((void**)&phi,   g_phi);  cudaGetSymbolAddress((void**)&plo,   g_plo);
    cudaGetSymbolAddress((void**)&fhi,   g_fhi);  cudaGetSymbolAddress((void**)&flo,   g_flo);
    cudaGetSymbolAddress((void**)&xhi,   g_xhi);  cudaGetSymbolAddress((void**)&xlo,   g_xlo);
    cudaGetSymbolAddress((void**)&w_in_h,  wb_in_hi);  cudaGetSymbolAddress((void**)&w_in_l,  wb_in_lo);
    cudaGetSymbolAddress((void**)&w_qkv_h, wb_qkv_hi); cudaGetSymbolAddress((void**)&w_qkv_l, wb_qkv_lo);
    cudaGetSymbolAddress((void**)&w_out_h, wb_out_hi); cudaGetSymbolAddress((void**)&w_out_l, wb_out_lo);
    cudaGetSymbolAddress((void**)&w_f1_h,  wb_f1_hi);  cudaGetSymbolAddress((void**)&w_f1_l,  wb_f1_lo);
    cudaGetSymbolAddress((void**)&w_f2_h,  wb_f2_hi);  cudaGetSymbolAddress((void**)&w_f2_l,  wb_f2_lo);
    cudaGetSymbolAddress((void**)&w_g1_h,  wb_g1_hi);  cudaGetSymbolAddress((void**)&w_g1_l,  wb_g1_lo);
    cudaGetSymbolAddress((void**)&w_g2_h,  wb_g2_hi);  cudaGetSymbolAddress((void**)&w_g2_l,  wb_g2_lo);

    cudaFuncSetAttribute(gemm_mma, cudaFuncAttributeMaxDynamicSharedMemorySize, SMEM_BYTES);
    cudaFuncSetAttribute(attn_flash, cudaFuncAttributeMaxDynamicSharedMemorySize, ATTN_SMEM);

    int nsm = 148;
    cudaDeviceGetAttribute(&nsm, cudaDevAttrMultiProcessorCount, 0);

    const int EW = 256;
    auto cvtgrid = [](int n) { return (n / 4 + 255) / 256; };

    // ---- weight + input hi/lo splits ----
    cvt_split4<<<cvtgrid(D*D),        EW>>>((const float4*)in_w,  (__nv_bfloat162*)w_in_h,  (__nv_bfloat162*)w_in_l,  D*D/4);
    cvt_split4<<<cvtgrid(LNUM*D3*D),  EW>>>((const float4*)qkv_w, (__nv_bfloat162*)w_qkv_h, (__nv_bfloat162*)w_qkv_l, LNUM*D3*D/4);
    cvt_split4<<<cvtgrid(LNUM*D*D),   EW>>>((const float4*)out_w, (__nv_bfloat162*)w_out_h, (__nv_bfloat162*)w_out_l, LNUM*D*D/4);
    cvt_split4<<<cvtgrid(LNUM*FFD*D), EW>>>((const float4*)ff_w1, (__nv_bfloat162*)w_f1_h,  (__nv_bfloat162*)w_f1_l,  LNUM*FFD*D/4);
    cvt_split4<<<cvtgrid(LNUM*D*FFD), EW>>>((const float4*)ff_w2, (__nv_bfloat162*)w_f2_h,  (__nv_bfloat162*)w_f2_l,  LNUM*D*FFD/4);
    cvt_split4<<<cvtgrid(LNUM*D3*D2), EW>>>((const float4*)g1_w,  (__nv_bfloat162*)w_g1_h,  (__nv_bfloat162*)w_g1_l,  LNUM*D3*D2/4);
    cvt_split4<<<cvtgrid(LNUM*D3*D2), EW>>>((const float4*)g2_w,  (__nv_bfloat162*)w_g2_h,  (__nv_bfloat162*)w_g2_l,  LNUM*D3*D2/4);
    cvt_split4<<<cvtgrid(NTOK*D),     EW>>>((const float4*)x_in,  (__nv_bfloat162*)xhi,     (__nv_bfloat162*)xlo,     NTOK*D/4);

    // tile grids: (gx columns, total tiles); persistent launch = min(ntiles, nsm)
    const int gxD  = D   / 128, ntD  = gxD  * (NTOK / 128);   // 8  x 16 = 128
    const int gxD3 = D3  / 128, ntD3 = gxD3 * (NTOK / 128);   // 24 x 16 = 384
    const int gxFF = FFD / 128, ntFF = gxFF * (NTOK / 128);   // 32 x 16 = 512
    const int cD   = ntD  < nsm ? ntD  : nsm;
    const int cD3  = ntD3 < nsm ? ntD3 : nsm;
    const int cFF  = ntFF < nsm ? ntFF : nsm;

    // ---- input projection, then fused gelu+pe+LN1+splits ----
    gemm_mma<<<cD, 256, SMEM_BYTES>>>(xhi, xlo, D, w_in_h, w_in_l, in_b, px, 0, 0, D, D, 0, gxD, ntD);
    gelu_pe_ln_split<<<NTOK, 256>>>(px, pe, ln1_g, ln1_b, chi, clo, lhi, llo);

    for (int l = 0; l < LNUM; l++) {
        const __nv_bfloat16* qwh = w_qkv_h + (size_t)l*D3*D;  const __nv_bfloat16* qwl = w_qkv_l + (size_t)l*D3*D;
        const __nv_bfloat16* owh = w_out_h + (size_t)l*D*D;   const __nv_bfloat16* owl = w_out_l + (size_t)l*D*D;
        const __nv_bfloat16* f1h = w_f1_h  + (size_t)l*FFD*D; const __nv_bfloat16* f1l = w_f1_l  + (size_t)l*FFD*D;
        const __nv_bfloat16* f2h = w_f2_h  + (size_t)l*D*FFD; const __nv_bfloat16* f2l = w_f2_l  + (size_t)l*D*FFD;
        const __nv_bfloat16* g1h = w_g1_h  + (size_t)l*D3*D2; const __nv_bfloat16* g1l = w_g1_l  + (size_t)l*D3*D2;
        const __nv_bfloat16* g2h = w_g2_h  + (size_t)l*D3*D2; const __nv_bfloat16* g2l = w_g2_l  + (size_t)l*D3*D2;
        const float* ob  = out_b + (size_t)l*D;
        const float* l2g = ln2_g + (size_t)l*D;  const float* l2b = ln2_b + (size_t)l*D;
        const float* fb1 = ff_b1 + (size_t)l*FFD;
        const float* fb2 = ff_b2 + (size_t)l*D;
        const float* gb1 = g1_bg + (size_t)l*D;
        const float* gb2 = g2_bg + (size_t)l*D;
        const float* ng = (l + 1 < LNUM) ? ln1_g + (size_t)(l+1)*D : on_g;
        const float* nb = (l + 1 < LNUM) ? ln1_b + (size_t)(l+1)*D : on_b;
        float* fout = (l + 1 < LNUM) ? nullptr : (float*)d_out;

        // attention block
        gemm_mma<<<cD3, 256, SMEM_BYTES>>>(lhi, llo, D, qwh, qwl, nullptr, pqkv, 0, 0, D3, D, 0, gxD3, ntD3);
        attn_flash<<<dim3(TT/QTILE, BATCH*H), 256, ATTN_SMEM>>>(pqkv, phi, plo);
        gemm_mma<<<cD, 256, SMEM_BYTES>>>(phi, plo, D, owh, owl, ob, 0, chi + D, clo + D, D2, D, 2, gxD, ntD);
        gemm_mma<<<cD3, 256, SMEM_BYTES>>>(chi, clo, D2, g1h, g1l, nullptr, pgate, 0, 0, D3, D2, 0, gxD3, ntD3);
        gru_ln_split<<<NTOK, 256>>>(px, pgate, gb1, l2g, l2b, chi, clo, lhi, llo, nullptr);

        // feed-forward block
        gemm_mma<<<cFF, 256, SMEM_BYTES>>>(lhi, llo, D, f1h, f1l, fb1, 0, fhi, flo, FFD, D, 1, gxFF, ntFF);
        gemm_mma<<<cD, 256, SMEM_BYTES>>>(fhi, flo, FFD, f2h, f2l, fb2, 0, chi + D, clo + D, D2, FFD, 2, gxD, ntD);
        gemm_mma<<<cD3, 256, SMEM_BYTES>>>(chi, clo, D2, g2h, g2l, nullptr, pgate, 0, 0, D3, D2, 0, gxD3, ntD3);
        gru_ln_split<<<NTOK, 256>>>(px, pgate, gb2, ng, nb, chi, clo, lhi, llo, fout);
    }
}

// round 9
// speedup vs baseline: 1.0247x; 1.0026x over previous
#include <cuda_runtime.h>
#include <cuda_bf16.h>
#include <math.h>
#include <stdint.h>

// ---------------- problem constants ----------------
#define LNUM  6
#define D     1024
#define H     16
#define DKH   64
#define FFD   4096
#define TT    1024
#define BATCH 2
#define NTOK  2048
#define D3    3072
#define D2    2048
#define ATT_SCALE 0.125f

#define SWZ(o) ((o) ^ (((o) >> 3) & 0x70))

// ---------------- scratch (device globals; no allocs allowed) ----------------
__device__ float g_x   [NTOK*D];     // residual stream (f32)
__device__ float g_qkv [NTOK*D3];
__device__ float g_gate[NTOK*D3];
__device__ __nv_bfloat16 g_chi[NTOK*D2],  g_clo[NTOK*D2];   // concat [x,y] hi/lo
__device__ __nv_bfloat16 g_lhi[NTOK*D],   g_llo[NTOK*D];    // LN output hi/lo
__device__ __nv_bfloat16 g_phi[NTOK*D],   g_plo[NTOK*D];    // attn output hi/lo
__device__ __nv_bfloat16 g_fhi[NTOK*FFD], g_flo[NTOK*FFD];  // FF hidden hi/lo
__device__ __nv_bfloat16 g_xhi[NTOK*D],   g_xlo[NTOK*D];    // input x split
__device__ __nv_bfloat16 wb_in_hi [D*D],        wb_in_lo [D*D];
__device__ __nv_bfloat16 wb_qkv_hi[LNUM*D3*D],  wb_qkv_lo[LNUM*D3*D];
__device__ __nv_bfloat16 wb_out_hi[LNUM*D*D],   wb_out_lo[LNUM*D*D];
__device__ __nv_bfloat16 wb_f1_hi [LNUM*FFD*D], wb_f1_lo [LNUM*FFD*D];
__device__ __nv_bfloat16 wb_f2_hi [LNUM*D*FFD], wb_f2_lo [LNUM*D*FFD];
__device__ __nv_bfloat16 wb_g1_hi [LNUM*D3*D2], wb_g1_lo [LNUM*D3*D2];
__device__ __nv_bfloat16 wb_g2_hi [LNUM*D3*D2], wb_g2_lo [LNUM*D3*D2];

// ---------------- PTX helpers (portable: sm_80-level) ----------------
__device__ __forceinline__ uint32_t smem_u32(const void* p) {
    uint32_t a;
    asm("{ .reg .u64 t; cvta.to.shared.u64 t, %1; cvt.u32.u64 %0, t; }" : "=r"(a) : "l"(p));
    return a;
}
__device__ __forceinline__ void cp16(uint32_t d, const void* g) {
    asm volatile("cp.async.cg.shared.global [%0], [%1], 16;" :: "r"(d), "l"(g));
}
__device__ __forceinline__ void ldm_x4(uint32_t* f, uint32_t addr) {
    asm volatile("ldmatrix.sync.aligned.m8n8.x4.shared.b16 {%0,%1,%2,%3}, [%4];"
                 : "=r"(f[0]), "=r"(f[1]), "=r"(f[2]), "=r"(f[3]) : "r"(addr));
}
__device__ __forceinline__ void mma16816(float* c, const uint32_t* a, uint32_t b0, uint32_t b1) {
    asm volatile(
        "mma.sync.aligned.m16n8k16.row.col.f32.bf16.bf16.f32 "
        "{%0,%1,%2,%3}, {%4,%5,%6,%7}, {%8,%9}, {%0,%1,%2,%3};"
        : "+f"(c[0]), "+f"(c[1]), "+f"(c[2]), "+f"(c[3])
        : "r"(a[0]), "r"(a[1]), "r"(a[2]), "r"(a[3]), "r"(b0), "r"(b1));
}
__device__ __forceinline__ float gelu_exact(float v) { return v * normcdff(v); }
__device__ __forceinline__ void split_bf16(float v, __nv_bfloat16& h, __nv_bfloat16& l) {
    h = __float2bfloat16(v);
    l = __float2bfloat16(v - __bfloat162float(h));
}

// ---------------- bf16 hi/lo split GEMM (persistent CTAs, cross-tile pipe) ---
#define STAGE_B 65536
#define SMEM_BYTES (2*STAGE_B)

__global__ __launch_bounds__(256)
void gemm_mma(const __nv_bfloat16* __restrict__ Ahi, const __nv_bfloat16* __restrict__ Alo,
              int lda,
              const __nv_bfloat16* __restrict__ Whi, const __nv_bfloat16* __restrict__ Wlo,
              const float* __restrict__ bias,
              float* __restrict__ Cf,
              __nv_bfloat16* __restrict__ Chi, __nv_bfloat16* __restrict__ Clo,
              int ldc, int K, int mode, int gx, int ntiles)
{
    extern __shared__ char smem[];
    const uint32_t sb = smem_u32(smem);
    const int tid  = threadIdx.x;
    const int wid  = tid >> 5;
    const int lane = tid & 31;
    const int wm   = wid >> 1;
    const int wn   = wid & 1;

    const int lr   = lane & 15;
    const int koff = (lane >> 4) << 4;
    uint32_t roffA[2], rxA[2], roffB[4], rxB[4];
#pragma unroll
    for (int i = 0; i < 2; i++) {
        int r = wm * 32 + i * 16 + lr;
        roffA[i] = r * 128; rxA[i] = (r & 7) << 4;
    }
#pragma unroll
    for (int j = 0; j < 4; j++) {
        int r = wn * 64 + j * 16 + lr;
        roffB[j] = r * 128; rxB[j] = (r & 7) << 4;
    }

    const int nch = K / 64;
    const int ldr = tid >> 3, ldc4 = tid & 7;

    auto issue = [&](int tt, int cc, int stage) {
        const int r0 = (tt / gx) * 128;
        const int c0 = (tt % gx) * 128;
        const int kbase = cc * 64;
        const uint32_t st = sb + stage * STAGE_B;
#pragma unroll
        for (int i = 0; i < 4; i++) {
            int r = ldr + i * 32;
            uint32_t off = SWZ((uint32_t)(r * 128 + ldc4 * 16));
            size_t sa = (size_t)(r0 + r) * lda + kbase + ldc4 * 8;
            size_t sw = (size_t)(c0 + r) * K   + kbase + ldc4 * 8;
            cp16(st +         off, Ahi + sa);
            cp16(st + 16384 + off, Alo + sa);
            cp16(st + 32768 + off, Whi + sw);
            cp16(st + 49152 + off, Wlo + sw);
        }
        asm volatile("cp.async.commit_group;");
    };

    const int grid = (int)gridDim.x;
    int cur_stage = 0;
    issue(blockIdx.x, 0, 0);

    for (int t = blockIdx.x; t < ntiles; t += grid) {
        const int row0 = (t / gx) * 128;
        const int col0 = (t % gx) * 128;

        float acc[2][8][4];
#pragma unroll
        for (int i = 0; i < 2; i++)
#pragma unroll
            for (int g = 0; g < 8; g++)
#pragma unroll
                for (int q = 0; q < 4; q++) acc[i][g][q] = 0.f;

        for (int cc = 0; cc < nch; cc++) {
            asm volatile("cp.async.wait_group 0;");
            __syncthreads();
            const int nxt = cur_stage ^ 1;
            if (cc + 1 < nch)              issue(t, cc + 1, nxt);
            else if (t + grid < ntiles)    issue(t + grid, 0, nxt);

            const uint32_t AH = sb + cur_stage * STAGE_B;
            const uint32_t AL = AH + 16384;
            const uint32_t WHs = AH + 32768;
            const uint32_t WLs = AH + 49152;
#pragma unroll
            for (int ks = 0; ks < 4; ks++) {
                const uint32_t kb = ks * 32 + koff;
                uint32_t ah[2][4], al[2][4];
#pragma unroll
                for (int i = 0; i < 2; i++) {
                    ldm_x4(ah[i], AH + roffA[i] + (kb ^ rxA[i]));
                    ldm_x4(al[i], AL + roffA[i] + (kb ^ rxA[i]));
                }
#pragma unroll
                for (int j = 0; j < 4; j++) {
                    uint32_t bh[4], bl[4];
                    ldm_x4(bh, WHs + roffB[j] + (kb ^ rxB[j]));
                    ldm_x4(bl, WLs + roffB[j] + (kb ^ rxB[j]));
#pragma unroll
                    for (int i = 0; i < 2; i++) {
                        mma16816(acc[i][j*2+0], ah[i], bh[0], bh[2]);
                        mma16816(acc[i][j*2+1], ah[i], bh[1], bh[3]);
                        mma16816(acc[i][j*2+0], ah[i], bl[0], bl[2]);
                        mma16816(acc[i][j*2+1], ah[i], bl[1], bl[3]);
                        mma16816(acc[i][j*2+0], al[i], bh[0], bh[2]);
                        mma16816(acc[i][j*2+1], al[i], bh[1], bh[3]);
                    }
                }
            }
            cur_stage ^= 1;
        }

        const int rbase = row0 + wm * 32 + (lane >> 2);
        const int cbase = wn * 64 + (lane & 3) * 2;
#pragma unroll
        for (int i = 0; i < 2; i++) {
#pragma unroll
            for (int g = 0; g < 8; g++) {
                const int c  = cbase + g * 8;
                const int cg = col0 + c;
                const int r0 = rbase + i * 16;
                float b0 = bias ? bias[cg]     : 0.f;
                float b1 = bias ? bias[cg + 1] : 0.f;
                float v00 = acc[i][g][0] + b0, v01 = acc[i][g][1] + b1;
                float v10 = acc[i][g][2] + b0, v11 = acc[i][g][3] + b1;
                if (mode == 0) {
                    *(float2*)(Cf + (size_t)r0 * ldc + cg)     = make_float2(v00, v01);
                    *(float2*)(Cf + (size_t)(r0+8) * ldc + cg) = make_float2(v10, v11);
                } else {
                    if (mode == 1) {
                        v00 = gelu_exact(v00); v01 = gelu_exact(v01);
                        v10 = gelu_exact(v10); v11 = gelu_exact(v11);
                    }
                    __nv_bfloat16 h00, l00, h01, l01, h10, l10, h11, l11;
                    split_bf16(v00, h00, l00); split_bf16(v01, h01, l01);
                    split_bf16(v10, h10, l10); split_bf16(v11, h11, l11);
                    *(__nv_bfloat162*)(Chi + (size_t)r0 * ldc + cg)     = __halves2bfloat162(h00, h01);
                    *(__nv_bfloat162*)(Chi + (size_t)(r0+8) * ldc + cg) = __halves2bfloat162(h10, h11);
                    *(__nv_bfloat162*)(Clo + (size_t)r0 * ldc + cg)     = __halves2bfloat162(l00, l01);
                    *(__nv_bfloat162*)(Clo + (size_t)(r0+8) * ldc + cg) = __halves2bfloat162(l10, l11);
                }
            }
        }
    }
}

// ---------------- flash attention v2: register-resident softmax --------------
// Row stats (m, l, rescale f) live in replicated registers of each 16-lane
// half-warp (a score row is owned entirely by one half-warp). Reductions via
// 4 shfl_xor. 3 __syncthreads per k-step (was ~7) and one smem pass over P
// (was 3 passes + stats arrays).
#define QTILE 128
#define KTILE 64
#define QP 68
#define KP 68
#define VP 68
#define SP 68
#define AQ_OFF 0
#define AK_OFF (AQ_OFF + 128*QP)
#define AV_OFF (AK_OFF + 64*KP)
#define AS_OFF (AV_OFF + 64*VP)
#define ATTN_SMEM ((AS_OFF + 128*SP) * 4)

__global__ __launch_bounds__(256)
void attn_flash(const float* __restrict__ qkv,
                __nv_bfloat16* __restrict__ ahi, __nv_bfloat16* __restrict__ alo) {
    extern __shared__ float sm[];
    float* Qs = sm + AQ_OFF;
    float* Kt = sm + AK_OFF;
    float* Vs = sm + AV_OFF;
    float* Ss = sm + AS_OFF;

    const int tid = threadIdx.x;
    const int tx = tid & 15, ty = tid >> 4;
    const int bh = blockIdx.y;
    const int b  = bh >> 4;
    const int h  = bh & 15;
    const int q0 = blockIdx.x * QTILE;

#pragma unroll
    for (int i = 0; i < 8; i++) {
        int idx = tid + i * 256;
        int r = idx >> 4, c = idx & 15;
        float4 v = *(const float4*)(qkv + ((size_t)((q0 + r) * BATCH + b)) * D3 + h * DKH + c * 4);
        v.x *= ATT_SCALE; v.y *= ATT_SCALE; v.z *= ATT_SCALE; v.w *= ATT_SCALE;
        *(float4*)(Qs + r * QP + c * 4) = v;
    }

    float acc[8][4];
    float mrow[8], lrow[8];
#pragma unroll
    for (int i = 0; i < 8; i++) {
        mrow[i] = -1e30f; lrow[i] = 0.f;
#pragma unroll
        for (int j = 0; j < 4; j++) acc[i][j] = 0.f;
    }

    __syncthreads();

    const int ntiles = blockIdx.x * 2 + 2;

    for (int kt = 0; kt < ntiles; kt++) {
        const int s0 = kt * KTILE;
        // ---- load K (transposed) and V tiles ----
#pragma unroll
        for (int i = 0; i < 4; i++) {
            int idx = tid + i * 256;
            int r = idx >> 4, c = idx & 15;
            const float* base = qkv + ((size_t)((s0 + r) * BATCH + b)) * D3 + h * DKH + c * 4;
            float4 kv = *(const float4*)(base + D);
            float4 vv = *(const float4*)(base + 2 * D);
            Kt[(c*4+0) * KP + r] = kv.x;
            Kt[(c*4+1) * KP + r] = kv.y;
            Kt[(c*4+2) * KP + r] = kv.z;
            Kt[(c*4+3) * KP + r] = kv.w;
            *(float4*)(Vs + r * VP + c * 4) = vv;
        }
        __syncthreads();

        // ---- scores in registers ----
        float sreg[8][4];
#pragma unroll
        for (int i = 0; i < 8; i++)
#pragma unroll
            for (int j = 0; j < 4; j++) sreg[i][j] = 0.f;
#pragma unroll 8
        for (int d = 0; d < 64; d++) {
            const float4 kq = *(const float4*)(Kt + d * KP + tx * 4);
#pragma unroll
            for (int i = 0; i < 8; i++) {
                float qv = Qs[(ty * 8 + i) * QP + d];
                sreg[i][0] += qv * kq.x;
                sreg[i][1] += qv * kq.y;
                sreg[i][2] += qv * kq.z;
                sreg[i][3] += qv * kq.w;
            }
        }
        // ---- causal mask in registers ----
#pragma unroll
        for (int i = 0; i < 8; i++) {
            const int qg = q0 + ty * 8 + i;
            if (s0 + tx*4 + 0 > qg) sreg[i][0] = -1e30f;
            if (s0 + tx*4 + 1 > qg) sreg[i][1] = -1e30f;
            if (s0 + tx*4 + 2 > qg) sreg[i][2] = -1e30f;
            if (s0 + tx*4 + 3 > qg) sreg[i][3] = -1e30f;
        }

        // ---- online softmax, stats in registers (half-warp shuffles) ----
        float frow[8];
#pragma unroll
        for (int i = 0; i < 8; i++) {
            float tmax = fmaxf(fmaxf(sreg[i][0], sreg[i][1]),
                               fmaxf(sreg[i][2], sreg[i][3]));
#pragma unroll
            for (int o = 8; o > 0; o >>= 1)
                tmax = fmaxf(tmax, __shfl_xor_sync(0xffffffffu, tmax, o));
            const float mn = fmaxf(mrow[i], tmax);
            frow[i] = __expf(mrow[i] - mn);
            mrow[i] = mn;
            float p0 = __expf(sreg[i][0] - mn);
            float p1 = __expf(sreg[i][1] - mn);
            float p2 = __expf(sreg[i][2] - mn);
            float p3 = __expf(sreg[i][3] - mn);
            float rs = p0 + p1 + p2 + p3;
#pragma unroll
            for (int o = 8; o > 0; o >>= 1)
                rs += __shfl_xor_sync(0xffffffffu, rs, o);
            lrow[i] = lrow[i] * frow[i] + rs;
            float4 o4 = make_float4(p0, p1, p2, p3);
            *(float4*)(Ss + (ty * 8 + i) * SP + tx * 4) = o4;
            // rescale accumulator
            acc[i][0] *= frow[i]; acc[i][1] *= frow[i];
            acc[i][2] *= frow[i]; acc[i][3] *= frow[i];
        }
        __syncthreads();

        // ---- P @ V ----
#pragma unroll 4
        for (int s = 0; s < 64; s++) {
            const float4 v4 = *(const float4*)(Vs + s * VP + tx * 4);
#pragma unroll
            for (int i = 0; i < 8; i++) {
                const float p = Ss[(ty * 8 + i) * SP + s];
                acc[i][0] += p * v4.x;
                acc[i][1] += p * v4.y;
                acc[i][2] += p * v4.z;
                acc[i][3] += p * v4.w;
            }
        }
        __syncthreads();
    }

#pragma unroll
    for (int i = 0; i < 8; i++) {
        const int q = ty * 8 + i;
        const float inv = 1.f / lrow[i];
        float v0 = acc[i][0] * inv, v1 = acc[i][1] * inv;
        float v2 = acc[i][2] * inv, v3 = acc[i][3] * inv;
        __nv_bfloat16 h0, l0, h1, l1, h2, l2, h3, l3;
        split_bf16(v0, h0, l0); split_bf16(v1, h1, l1);
        split_bf16(v2, h2, l2); split_bf16(v3, h3, l3);
        size_t base = ((size_t)((q0 + q) * BATCH + b)) * D + h * DKH + tx * 4;
        *(__nv_bfloat162*)(ahi + base)     = __halves2bfloat162(h0, h1);
        *(__nv_bfloat162*)(ahi + base + 2) = __halves2bfloat162(h2, h3);
        *(__nv_bfloat162*)(alo + base)     = __halves2bfloat162(l0, l1);
        *(__nv_bfloat162*)(alo + base + 2) = __halves2bfloat162(l2, l3);
    }
}

// ---------------- fused GRU + LN + splits (one block per token) --------------
__global__ __launch_bounds__(256)
void gru_ln_split(float* __restrict__ px, const float* __restrict__ gate,
                  const float* __restrict__ bg,
                  const float* __restrict__ g, const float* __restrict__ b,
                  __nv_bfloat16* __restrict__ cathi, __nv_bfloat16* __restrict__ catlo,
                  __nv_bfloat16* __restrict__ lnhi, __nv_bfloat16* __restrict__ lnlo,
                  float* __restrict__ outf) {
    const int n = blockIdx.x;
    const int tid = threadIdx.x;
    const float* grow = gate + (size_t)n * D3;
    float vals[4];
    float s = 0.f, sq = 0.f;
#pragma unroll
    for (int k = 0; k < 4; k++) {
        const int j = tid + k * 256;
        float gr = grow[j];
        float gz = grow[D + j];
        float gh = grow[2 * D + j];
        float r = 1.f / (1.f + __expf(-gr));
        float z = 1.f / (1.f + __expf(-(gz - bg[j])));
        float hh = tanhf(gh * r);
        float xv = px[(size_t)n * D + j];
        float v = (1.f - z) * xv + z * hh;
        px[(size_t)n * D + j] = v;
        vals[k] = v;
        __nv_bfloat16 h, l; split_bf16(v, h, l);
        cathi[(size_t)n * D2 + j] = h;
        catlo[(size_t)n * D2 + j] = l;
        s += v; sq += v * v;
    }
    __shared__ float rs[256], rq[256];
    rs[tid] = s; rq[tid] = sq; __syncthreads();
    for (int off = 128; off > 0; off >>= 1) {
        if (tid < off) { rs[tid] += rs[tid + off]; rq[tid] += rq[tid + off]; }
        __syncthreads();
    }
    const float mu  = rs[0] * (1.f / D);
    const float var = rq[0] * (1.f / D) - mu * mu;
    const float inv = rsqrtf(var + 1e-6f);
#pragma unroll
    for (int k = 0; k < 4; k++) {
        const int j = tid + k * 256;
        float y = (vals[k] - mu) * inv * g[j] + b[j];
        if (outf) {
            outf[(size_t)n * D + j] = y;
        } else {
            __nv_bfloat16 h, l; split_bf16(y, h, l);
            lnhi[(size_t)n * D + j] = h;
            lnlo[(size_t)n * D + j] = l;
        }
    }
}

// ---------------- fused GELU+PE + LN + splits (layer-0 entry) ----------------
__global__ __launch_bounds__(256)
void gelu_pe_ln_split(float* __restrict__ px, const float* __restrict__ pe,
                      const float* __restrict__ g, const float* __restrict__ b,
                      __nv_bfloat16* __restrict__ cathi, __nv_bfloat16* __restrict__ catlo,
                      __nv_bfloat16* __restrict__ lnhi, __nv_bfloat16* __restrict__ lnlo) {
    const int n = blockIdx.x;
    const int t = n >> 1;
    const int tid = threadIdx.x;
    float vals[4];
    float s = 0.f, sq = 0.f;
#pragma unroll
    for (int k = 0; k < 4; k++) {
        const int j = tid + k * 256;
        float v = gelu_exact(px[(size_t)n * D + j]) + pe[(size_t)t * D + j];
        px[(size_t)n * D + j] = v;
        vals[k] = v;
        __nv_bfloat16 h, l; split_bf16(v, h, l);
        cathi[(size_t)n * D2 + j] = h;
        catlo[(size_t)n * D2 + j] = l;
        s += v; sq += v * v;
    }
    __shared__ float rs[256], rq[256];
    rs[tid] = s; rq[tid] = sq; __syncthreads();
    for (int off = 128; off > 0; off >>= 1) {
        if (tid < off) { rs[tid] += rs[tid + off]; rq[tid] += rq[tid + off]; }
        __syncthreads();
    }
    const float mu  = rs[0] * (1.f / D);
    const float var = rq[0] * (1.f / D) - mu * mu;
    const float inv = rsqrtf(var + 1e-6f);
#pragma unroll
    for (int k = 0; k < 4; k++) {
        const int j = tid + k * 256;
        float y = (vals[k] - mu) * inv * g[j] + b[j];
        __nv_bfloat16 h, l; split_bf16(y, h, l);
        lnhi[(size_t)n * D + j] = h;
        lnlo[(size_t)n * D + j] = l;
    }
}

// ---------------- f32 -> hi/lo bf16 split (weights + input) ----------------
__global__ void cvt_split4(const float4* __restrict__ x,
                           __nv_bfloat162* __restrict__ hi, __nv_bfloat162* __restrict__ lo,
                           int n4) {
    int i = blockIdx.x * blockDim.x + threadIdx.x;
    if (i >= n4) return;
    float4 v = x[i];
    __nv_bfloat16 h0, l0, h1, l1, h2, l2, h3, l3;
    split_bf16(v.x, h0, l0); split_bf16(v.y, h1, l1);
    split_bf16(v.z, h2, l2); split_bf16(v.w, h3, l3);
    hi[2*i]   = __halves2bfloat162(h0, h1);
    hi[2*i+1] = __halves2bfloat162(h2, h3);
    lo[2*i]   = __halves2bfloat162(l0, l1);
    lo[2*i+1] = __halves2bfloat162(l2, l3);
}

// ---------------- driver ----------------
extern "C" void kernel_launch(void* const* d_in, const int* in_sizes, int n_in,
                              void* d_out, int out_size) {
    const float* x_in  = (const float*)d_in[0];
    const float* pe    = (const float*)d_in[1];
    const float* in_w  = (const float*)d_in[2];
    const float* in_b  = (const float*)d_in[3];
    const float* qkv_w = (const float*)d_in[4];
    const float* out_w = (const float*)d_in[5];
    const float* out_b = (const float*)d_in[6];
    const float* ln1_g = (const float*)d_in[7];
    const float* ln1_b = (const float*)d_in[8];
    const float* ln2_g = (const float*)d_in[9];
    const float* ln2_b = (const float*)d_in[10];
    const float* ff_w1 = (const float*)d_in[11];
    const float* ff_b1 = (const float*)d_in[12];
    const float* ff_w2 = (const float*)d_in[13];
    const float* ff_b2 = (const float*)d_in[14];
    const float* g1_w  = (const float*)d_in[15];
    const float* g1_bg = (const float*)d_in[16];
    const float* g2_w  = (const float*)d_in[17];
    const float* g2_bg = (const float*)d_in[18];
    const float* on_g  = (const float*)d_in[19];
    const float* on_b  = (const float*)d_in[20];

    float *px, *pqkv, *pgate;
    __nv_bfloat16 *chi, *clo, *lhi, *llo, *phi, *plo, *fhi, *flo, *xhi, *xlo;
    __nv_bfloat16 *w_in_h, *w_in_l, *w_qkv_h, *w_qkv_l, *w_out_h, *w_out_l;
    __nv_bfloat16 *w_f1_h, *w_f1_l, *w_f2_h, *w_f2_l, *w_g1_h, *w_g1_l, *w_g2_h, *w_g2_l;
    cudaGetSymbolAddress((void**)&px,    g_x);
    cudaGetSymbolAddress((void**)&pqkv,  g_qkv);
    cudaGetSymbolAddress((void**)&pgate, g_gate);
    cudaGetSymbolAddress((void**)&chi,   g_chi);  cudaGetSymbolAddress((void**)&clo,   g_clo);
    cudaGetSymbolAddress((void**)&lhi,   g_lhi);  cudaGetSymbolAddress((void**)&llo,   g_llo);
    cudaGetSymbolAddress((void**)&phi,   g_phi);  cudaGetSymbolAddress((void**)&plo,   g_plo);
    cudaGetSymbolAddress((void**)&fhi,   g_fhi);  cudaGetSymbolAddress((void**)&flo,   g_flo);
    cudaGetSymbolAddress((void**)&xhi,   g_xhi);  cudaGetSymbolAddress((void**)&xlo,   g_xlo);
    cudaGetSymbolAddress((void**)&w_in_h,  wb_in_hi);  cudaGetSymbolAddress((void**)&w_in_l,  wb_in_lo);
    cudaGetSymbolAddress((void**)&w_qkv_h, wb_qkv_hi); cudaGetSymbolAddress((void**)&w_qkv_l, wb_qkv_lo);
    cudaGetSymbolAddress((void**)&w_out_h, wb_out_hi); cudaGetSymbolAddress((void**)&w_out_l, wb_out_lo);
    cudaGetSymbolAddress((void**)&w_f1_h,  wb_f1_hi);  cudaGetSymbolAddress((void**)&w_f1_l,  wb_f1_lo);
    cudaGetSymbolAddress((void**)&w_f2_h,  wb_f2_hi);  cudaGetSymbolAddress((void**)&w_f2_l,  wb_f2_lo);
    cudaGetSymbolAddress((void**)&w_g1_h,  wb_g1_hi);  cudaGetSymbolAddress((void**)&w_g1_l,  wb_g1_lo);
    cudaGetSymbolAddress((void**)&w_g2_h,  wb_g2_hi);  cudaGetSymbolAddress((void**)&w_g2_l,  wb_g2_lo);

    cudaFuncSetAttribute(gemm_mma, cudaFuncAttributeMaxDynamicSharedMemorySize, SMEM_BYTES);
    cudaFuncSetAttribute(attn_flash, cudaFuncAttributeMaxDynamicSharedMemorySize, ATTN_SMEM);

    int nsm = 148;
    cudaDeviceGetAttribute(&nsm, cudaDevAttrMultiProcessorCount, 0);

    const int EW = 256;
    auto cvtgrid = [](int n) { return (n / 4 + 255) / 256; };

    // ---- weight + input hi/lo splits ----
    cvt_split4<<<cvtgrid(D*D),        EW>>>((const float4*)in_w,  (__nv_bfloat162*)w_in_h,  (__nv_bfloat162*)w_in_l,  D*D/4);
    cvt_split4<<<cvtgrid(LNUM*D3*D),  EW>>>((const float4*)qkv_w, (__nv_bfloat162*)w_qkv_h, (__nv_bfloat162*)w_qkv_l, LNUM*D3*D/4);
    cvt_split4<<<cvtgrid(LNUM*D*D),   EW>>>((const float4*)out_w, (__nv_bfloat162*)w_out_h, (__nv_bfloat162*)w_out_l, LNUM*D*D/4);
    cvt_split4<<<cvtgrid(LNUM*FFD*D), EW>>>((const float4*)ff_w1, (__nv_bfloat162*)w_f1_h,  (__nv_bfloat162*)w_f1_l,  LNUM*FFD*D/4);
    cvt_split4<<<cvtgrid(LNUM*D*FFD), EW>>>((const float4*)ff_w2, (__nv_bfloat162*)w_f2_h,  (__nv_bfloat162*)w_f2_l,  LNUM*D*FFD/4);
    cvt_split4<<<cvtgrid(LNUM*D3*D2), EW>>>((const float4*)g1_w,  (__nv_bfloat162*)w_g1_h,  (__nv_bfloat162*)w_g1_l,  LNUM*D3*D2/4);
    cvt_split4<<<cvtgrid(LNUM*D3*D2), EW>>>((const float4*)g2_w,  (__nv_bfloat162*)w_g2_h,  (__nv_bfloat162*)w_g2_l,  LNUM*D3*D2/4);
    cvt_split4<<<cvtgrid(NTOK*D),     EW>>>((const float4*)x_in,  (__nv_bfloat162*)xhi,     (__nv_bfloat162*)xlo,     NTOK*D/4);

    const int gxD  = D   / 128, ntD  = gxD  * (NTOK / 128);
    const int gxD3 = D3  / 128, ntD3 = gxD3 * (NTOK / 128);
    const int gxFF = FFD / 128, ntFF = gxFF * (NTOK / 128);
    const int cD   = ntD  < nsm ? ntD  : nsm;
    const int cD3  = ntD3 < nsm ? ntD3 : nsm;
    const int cFF  = ntFF < nsm ? ntFF : nsm;

    gemm_mma<<<cD, 256, SMEM_BYTES>>>(xhi, xlo, D, w_in_h, w_in_l, in_b, px, 0, 0, D, D, 0, gxD, ntD);
    gelu_pe_ln_split<<<NTOK, 256>>>(px, pe, ln1_g, ln1_b, chi, clo, lhi, llo);

    for (int l = 0; l < LNUM; l++) {
        const __nv_bfloat16* qwh = w_qkv_h + (size_t)l*D3*D;  const __nv_bfloat16* qwl = w_qkv_l + (size_t)l*D3*D;
        const __nv_bfloat16* owh = w_out_h + (size_t)l*D*D;   const __nv_bfloat16* owl = w_out_l + (size_t)l*D*D;
        const __nv_bfloat16* f1h = w_f1_h  + (size_t)l*FFD*D; const __nv_bfloat16* f1l = w_f1_l  + (size_t)l*FFD*D;
        const __nv_bfloat16* f2h = w_f2_h  + (size_t)l*D*FFD; const __nv_bfloat16* f2l = w_f2_l  + (size_t)l*D*FFD;
        const __nv_bfloat16* g1h = w_g1_h  + (size_t)l*D3*D2; const __nv_bfloat16* g1l = w_g1_l  + (size_t)l*D3*D2;
        const __nv_bfloat16* g2h = w_g2_h  + (size_t)l*D3*D2; const __nv_bfloat16* g2l = w_g2_l  + (size_t)l*D3*D2;
        const float* ob  = out_b + (size_t)l*D;
        const float* l2g = ln2_g + (size_t)l*D;  const float* l2b = ln2_b + (size_t)l*D;
        const float* fb1 = ff_b1 + (size_t)l*FFD;
        const float* fb2 = ff_b2 + (size_t)l*D;
        const float* gb1 = g1_bg + (size_t)l*D;
        const float* gb2 = g2_bg + (size_t)l*D;
        const float* ng = (l + 1 < LNUM) ? ln1_g + (size_t)(l+1)*D : on_g;
        const float* nb = (l + 1 < LNUM) ? ln1_b + (size_t)(l+1)*D : on_b;
        float* fout = (l + 1 < LNUM) ? nullptr : (float*)d_out;

        // attention block
        gemm_mma<<<cD3, 256, SMEM_BYTES>>>(lhi, llo, D, qwh, qwl, nullptr, pqkv, 0, 0, D3, D, 0, gxD3, ntD3);
        attn_flash<<<dim3(TT/QTILE, BATCH*H), 256, ATTN_SMEM>>>(pqkv, phi, plo);
        gemm_mma<<<cD, 256, SMEM_BYTES>>>(phi, plo, D, owh, owl, ob, 0, chi + D, clo + D, D2, D, 2, gxD, ntD);
        gemm_mma<<<cD3, 256, SMEM_BYTES>>>(chi, clo, D2, g1h, g1l, nullptr, pgate, 0, 0, D3, D2, 0, gxD3, ntD3);
        gru_ln_split<<<NTOK, 256>>>(px, pgate, gb1, l2g, l2b, chi, clo, lhi, llo, nullptr);

        // feed-forward block
        gemm_mma<<<cFF, 256, SMEM_BYTES>>>(lhi, llo, D, f1h, f1l, fb1, 0, fhi, flo, FFD, D, 1, gxFF, ntFF);
        gemm_mma<<<cD, 256, SMEM_BYTES>>>(fhi, flo, FFD, f2h, f2l, fb2, 0, chi + D, clo + D, D2, FFD, 2, gxD, ntD);
        gemm_mma<<<cD3, 256, SMEM_BYTES>>>(chi, clo, D2, g2h, g2l, nullptr, pgate, 0, 0, D3, D2, 0, gxD3, ntD3);
        gru_ln_split<<<NTOK, 256>>>(px, pgate, gb2, ng, nb, chi, clo, lhi, llo, fout);
    }
}

// round 10
// speedup vs baseline: 1.2629x; 1.2324x over previous
#include <cuda_runtime.h>
#include <cuda_fp16.h>
#include <math.h>
#include <stdint.h>

// ---------------- problem constants ----------------
#define LNUM  6
#define D     1024
#define H     16
#define DKH   64
#define FFD   4096
#define TT    1024
#define BATCH 2
#define NTOK  2048
#define D3    3072
#define D2    2048
#define ATT_SCALE 0.125f
#define SCL   0.015625f        // 2^-6
#define SCLI  64.0f            // 2^6

#define SWZ(o) ((o) ^ (((o) >> 3) & 0x70))

// ---------------- scratch (device globals; no allocs allowed) ----------------
__device__ float g_x   [NTOK*D];     // residual stream (f32)
__device__ float g_qkv [NTOK*D3];
__device__ float g_gate[NTOK*D3];
__device__ __half g_chi[NTOK*D2],  g_clo[NTOK*D2];   // concat [x,y] hi / A2
__device__ __half g_lhi[NTOK*D],   g_llo[NTOK*D];    // LN output hi / A2
__device__ __half g_phi[NTOK*D],   g_plo[NTOK*D];    // attn output hi / A2
__device__ __half g_fhi[NTOK*FFD], g_flo[NTOK*FFD];  // FF hidden hi / A2
__device__ __half g_xhi[NTOK*D],   g_xlo[NTOK*D];    // input x split
__device__ __half wb_in_hi [D*D],        wb_in_lo [D*D];
__device__ __half wb_qkv_hi[LNUM*D3*D],  wb_qkv_lo[LNUM*D3*D];
__device__ __half wb_out_hi[LNUM*D*D],   wb_out_lo[LNUM*D*D];
__device__ __half wb_f1_hi [LNUM*FFD*D], wb_f1_lo [LNUM*FFD*D];
__device__ __half wb_f2_hi [LNUM*D*FFD], wb_f2_lo [LNUM*D*FFD];
__device__ __half wb_g1_hi [LNUM*D3*D2], wb_g1_lo [LNUM*D3*D2];
__device__ __half wb_g2_hi [LNUM*D3*D2], wb_g2_lo [LNUM*D3*D2];

// ---------------- PTX helpers (portable: sm_80-level) ----------------
__device__ __forceinline__ uint32_t smem_u32(const void* p) {
    uint32_t a;
    asm("{ .reg .u64 t; cvta.to.shared.u64 t, %1; cvt.u32.u64 %0, t; }" : "=r"(a) : "l"(p));
    return a;
}
__device__ __forceinline__ void cp16(uint32_t d, const void* g) {
    asm volatile("cp.async.cg.shared.global [%0], [%1], 16;" :: "r"(d), "l"(g));
}
__device__ __forceinline__ void ldm_x4(uint32_t* f, uint32_t addr) {
    asm volatile("ldmatrix.sync.aligned.m8n8.x4.shared.b16 {%0,%1,%2,%3}, [%4];"
                 : "=r"(f[0]), "=r"(f[1]), "=r"(f[2]), "=r"(f[3]) : "r"(addr));
}
__device__ __forceinline__ void mma16816(float* c, const uint32_t* a, uint32_t b0, uint32_t b1) {
    asm volatile(
        "mma.sync.aligned.m16n8k16.row.col.f32.f16.f16.f32 "
        "{%0,%1,%2,%3}, {%4,%5,%6,%7}, {%8,%9}, {%0,%1,%2,%3};"
        : "+f"(c[0]), "+f"(c[1]), "+f"(c[2]), "+f"(c[3])
        : "r"(a[0]), "r"(a[1]), "r"(a[2]), "r"(a[3]), "r"(b0), "r"(b1));
}
__device__ __forceinline__ float gelu_exact(float v) { return v * normcdff(v); }

// Activation split: hi = fp16(v); A2 = fp16((v - hi) + hi*2^-6)
__device__ __forceinline__ void split_act(float v, __half& h, __half& a2) {
    h = __float2half_rn(v);
    float lo = v - __half2float(h);
    a2 = __float2half_rn(fmaf(__half2float(h), SCL, lo));
}
// Weight split: hi = fp16(w); W2 = fp16(hi + (w - hi)*2^6)
__device__ __forceinline__ void split_wgt(float w, __half& h, __half& w2) {
    h = __float2half_rn(w);
    float lo = w - __half2float(h);
    w2 = __float2half_rn(fmaf(lo, SCLI, __half2float(h)));
}
// Final combine: C = acc1*(1 - 2^-6) + acc2
__device__ __forceinline__ float combine(float a1, float a2) {
    return fmaf(a1, 1.0f - SCL, a2);
}

// ---------------- fp16 2-MMA GEMM (persistent CTAs, cross-tile pipe) ---------
// C[NTOK,ncols] = A[NTOK,K] @ W[ncols,K]^T via T1=Ahi·Whi, T2=A2·W2,
// C = (1-2^-6)·T1 + T2.  mode 0: f32 out (+bias). 1: gelu->pairs. 2: ->pairs.
#define STAGE_B 65536
#define SMEM_BYTES (2*STAGE_B)

__global__ __launch_bounds__(256)
void gemm_mma(const __half* __restrict__ Ahi, const __half* __restrict__ A2p,
              int lda,
              const __half* __restrict__ Whi, const __half* __restrict__ W2p,
              const float* __restrict__ bias,
              float* __restrict__ Cf,
              __half* __restrict__ Chi, __half* __restrict__ Clo,
              int ldc, int K, int mode, int gx, int ntiles)
{
    extern __shared__ char smem[];
    const uint32_t sb = smem_u32(smem);
    const int tid  = threadIdx.x;
    const int wid  = tid >> 5;
    const int lane = tid & 31;
    const int wm   = wid >> 1;
    const int wn   = wid & 1;

    const int lr   = lane & 15;
    const int koff = (lane >> 4) << 4;
    uint32_t roffA[2], rxA[2], roffB[4], rxB[4];
#pragma unroll
    for (int i = 0; i < 2; i++) {
        int r = wm * 32 + i * 16 + lr;
        roffA[i] = r * 128; rxA[i] = (r & 7) << 4;
    }
#pragma unroll
    for (int j = 0; j < 4; j++) {
        int r = wn * 64 + j * 16 + lr;
        roffB[j] = r * 128; rxB[j] = (r & 7) << 4;
    }

    const int nch = K / 64;
    const int ldr = tid >> 3, ldc4 = tid & 7;

    auto issue = [&](int tt, int cc, int stage) {
        const int r0 = (tt / gx) * 128;
        const int c0 = (tt % gx) * 128;
        const int kbase = cc * 64;
        const uint32_t st = sb + stage * STAGE_B;
#pragma unroll
        for (int i = 0; i < 4; i++) {
            int r = ldr + i * 32;
            uint32_t off = SWZ((uint32_t)(r * 128 + ldc4 * 16));
            size_t sa = (size_t)(r0 + r) * lda + kbase + ldc4 * 8;
            size_t sw = (size_t)(c0 + r) * K   + kbase + ldc4 * 8;
            cp16(st +         off, Ahi + sa);
            cp16(st + 16384 + off, A2p + sa);
            cp16(st + 32768 + off, Whi + sw);
            cp16(st + 49152 + off, W2p + sw);
        }
        asm volatile("cp.async.commit_group;");
    };

    const int grid = (int)gridDim.x;
    int cur_stage = 0;
    issue(blockIdx.x, 0, 0);

    for (int t = blockIdx.x; t < ntiles; t += grid) {
        const int row0 = (t / gx) * 128;
        const int col0 = (t % gx) * 128;

        float acc1[2][8][4], acc2[2][8][4];
#pragma unroll
        for (int i = 0; i < 2; i++)
#pragma unroll
            for (int g = 0; g < 8; g++)
#pragma unroll
                for (int q = 0; q < 4; q++) { acc1[i][g][q] = 0.f; acc2[i][g][q] = 0.f; }

        for (int cc = 0; cc < nch; cc++) {
            asm volatile("cp.async.wait_group 0;");
            __syncthreads();
            const int nxt = cur_stage ^ 1;
            if (cc + 1 < nch)              issue(t, cc + 1, nxt);
            else if (t + grid < ntiles)    issue(t + grid, 0, nxt);

            const uint32_t AH = sb + cur_stage * STAGE_B;
            const uint32_t AL = AH + 16384;
            const uint32_t WHs = AH + 32768;
            const uint32_t WLs = AH + 49152;
#pragma unroll
            for (int ks = 0; ks < 4; ks++) {
                const uint32_t kb = ks * 32 + koff;
                uint32_t ah[2][4], a2[2][4];
#pragma unroll
                for (int i = 0; i < 2; i++) {
                    ldm_x4(ah[i], AH + roffA[i] + (kb ^ rxA[i]));
                    ldm_x4(a2[i], AL + roffA[i] + (kb ^ rxA[i]));
                }
#pragma unroll
                for (int j = 0; j < 4; j++) {
                    uint32_t bh[4], b2[4];
                    ldm_x4(bh, WHs + roffB[j] + (kb ^ rxB[j]));
                    ldm_x4(b2, WLs + roffB[j] + (kb ^ rxB[j]));
#pragma unroll
                    for (int i = 0; i < 2; i++) {
                        mma16816(acc1[i][j*2+0], ah[i], bh[0], bh[2]);
                        mma16816(acc1[i][j*2+1], ah[i], bh[1], bh[3]);
                        mma16816(acc2[i][j*2+0], a2[i], b2[0], b2[2]);
                        mma16816(acc2[i][j*2+1], a2[i], b2[1], b2[3]);
                    }
                }
            }
            cur_stage ^= 1;
        }

        const int rbase = row0 + wm * 32 + (lane >> 2);
        const int cbase = wn * 64 + (lane & 3) * 2;
#pragma unroll
        for (int i = 0; i < 2; i++) {
#pragma unroll
            for (int g = 0; g < 8; g++) {
                const int c  = cbase + g * 8;
                const int cg = col0 + c;
                const int r0 = rbase + i * 16;
                float b0 = bias ? bias[cg]     : 0.f;
                float b1 = bias ? bias[cg + 1] : 0.f;
                float v00 = combine(acc1[i][g][0], acc2[i][g][0]) + b0;
                float v01 = combine(acc1[i][g][1], acc2[i][g][1]) + b1;
                float v10 = combine(acc1[i][g][2], acc2[i][g][2]) + b0;
                float v11 = combine(acc1[i][g][3], acc2[i][g][3]) + b1;
                if (mode == 0) {
                    *(float2*)(Cf + (size_t)r0 * ldc + cg)     = make_float2(v00, v01);
                    *(float2*)(Cf + (size_t)(r0+8) * ldc + cg) = make_float2(v10, v11);
                } else {
                    if (mode == 1) {
                        v00 = gelu_exact(v00); v01 = gelu_exact(v01);
                        v10 = gelu_exact(v10); v11 = gelu_exact(v11);
                    }
                    __half h00, l00, h01, l01, h10, l10, h11, l11;
                    split_act(v00, h00, l00); split_act(v01, h01, l01);
                    split_act(v10, h10, l10); split_act(v11, h11, l11);
                    *(__half2*)(Chi + (size_t)r0 * ldc + cg)     = __halves2half2(h00, h01);
                    *(__half2*)(Chi + (size_t)(r0+8) * ldc + cg) = __halves2half2(h10, h11);
                    *(__half2*)(Clo + (size_t)r0 * ldc + cg)     = __halves2half2(l00, l01);
                    *(__half2*)(Clo + (size_t)(r0+8) * ldc + cg) = __halves2half2(l10, l11);
                }
            }
        }
    }
}

// ---------------- flash attention (register softmax, fp16-pair out) ----------
#define QTILE 128
#define KTILE 64
#define QP 68
#define KP 68
#define VP 68
#define SP 68
#define AQ_OFF 0
#define AK_OFF (AQ_OFF + 128*QP)
#define AV_OFF (AK_OFF + 64*KP)
#define AS_OFF (AV_OFF + 64*VP)
#define ATTN_SMEM ((AS_OFF + 128*SP) * 4)

__global__ __launch_bounds__(256)
void attn_flash(const float* __restrict__ qkv,
                __half* __restrict__ ahi, __half* __restrict__ alo) {
    extern __shared__ float sm[];
    float* Qs = sm + AQ_OFF;
    float* Kt = sm + AK_OFF;
    float* Vs = sm + AV_OFF;
    float* Ss = sm + AS_OFF;

    const int tid = threadIdx.x;
    const int tx = tid & 15, ty = tid >> 4;
    const int bh = blockIdx.y;
    const int b  = bh >> 4;
    const int h  = bh & 15;
    const int q0 = blockIdx.x * QTILE;

#pragma unroll
    for (int i = 0; i < 8; i++) {
        int idx = tid + i * 256;
        int r = idx >> 4, c = idx & 15;
        float4 v = *(const float4*)(qkv + ((size_t)((q0 + r) * BATCH + b)) * D3 + h * DKH + c * 4);
        v.x *= ATT_SCALE; v.y *= ATT_SCALE; v.z *= ATT_SCALE; v.w *= ATT_SCALE;
        *(float4*)(Qs + r * QP + c * 4) = v;
    }

    float acc[8][4];
    float mrow[8], lrow[8];
#pragma unroll
    for (int i = 0; i < 8; i++) {
        mrow[i] = -1e30f; lrow[i] = 0.f;
#pragma unroll
        for (int j = 0; j < 4; j++) acc[i][j] = 0.f;
    }

    __syncthreads();

    const int ntiles = blockIdx.x * 2 + 2;

    for (int kt = 0; kt < ntiles; kt++) {
        const int s0 = kt * KTILE;
#pragma unroll
        for (int i = 0; i < 4; i++) {
            int idx = tid + i * 256;
            int r = idx >> 4, c = idx & 15;
            const float* base = qkv + ((size_t)((s0 + r) * BATCH + b)) * D3 + h * DKH + c * 4;
            float4 kv = *(const float4*)(base + D);
            float4 vv = *(const float4*)(base + 2 * D);
            Kt[(c*4+0) * KP + r] = kv.x;
            Kt[(c*4+1) * KP + r] = kv.y;
            Kt[(c*4+2) * KP + r] = kv.z;
            Kt[(c*4+3) * KP + r] = kv.w;
            *(float4*)(Vs + r * VP + c * 4) = vv;
        }
        __syncthreads();

        float sreg[8][4];
#pragma unroll
        for (int i = 0; i < 8; i++)
#pragma unroll
            for (int j = 0; j < 4; j++) sreg[i][j] = 0.f;
#pragma unroll 8
        for (int d = 0; d < 64; d++) {
            const float4 kq = *(const float4*)(Kt + d * KP + tx * 4);
#pragma unroll
            for (int i = 0; i < 8; i++) {
                float qv = Qs[(ty * 8 + i) * QP + d];
                sreg[i][0] += qv * kq.x;
                sreg[i][1] += qv * kq.y;
                sreg[i][2] += qv * kq.z;
                sreg[i][3] += qv * kq.w;
            }
        }
#pragma unroll
        for (int i = 0; i < 8; i++) {
            const int qg = q0 + ty * 8 + i;
            if (s0 + tx*4 + 0 > qg) sreg[i][0] = -1e30f;
            if (s0 + tx*4 + 1 > qg) sreg[i][1] = -1e30f;
            if (s0 + tx*4 + 2 > qg) sreg[i][2] = -1e30f;
            if (s0 + tx*4 + 3 > qg) sreg[i][3] = -1e30f;
        }

        float frow[8];
#pragma unroll
        for (int i = 0; i < 8; i++) {
            float tmax = fmaxf(fmaxf(sreg[i][0], sreg[i][1]),
                               fmaxf(sreg[i][2], sreg[i][3]));
#pragma unroll
            for (int o = 8; o > 0; o >>= 1)
                tmax = fmaxf(tmax, __shfl_xor_sync(0xffffffffu, tmax, o));
            const float mn = fmaxf(mrow[i], tmax);
            frow[i] = __expf(mrow[i] - mn);
            mrow[i] = mn;
            float p0 = __expf(sreg[i][0] - mn);
            float p1 = __expf(sreg[i][1] - mn);
            float p2 = __expf(sreg[i][2] - mn);
            float p3 = __expf(sreg[i][3] - mn);
            float rs = p0 + p1 + p2 + p3;
#pragma unroll
            for (int o = 8; o > 0; o >>= 1)
                rs += __shfl_xor_sync(0xffffffffu, rs, o);
            lrow[i] = lrow[i] * frow[i] + rs;
            *(float4*)(Ss + (ty * 8 + i) * SP + tx * 4) = make_float4(p0, p1, p2, p3);
            acc[i][0] *= frow[i]; acc[i][1] *= frow[i];
            acc[i][2] *= frow[i]; acc[i][3] *= frow[i];
        }
        __syncthreads();

#pragma unroll 4
        for (int s = 0; s < 64; s++) {
            const float4 v4 = *(const float4*)(Vs + s * VP + tx * 4);
#pragma unroll
            for (int i = 0; i < 8; i++) {
                const float p = Ss[(ty * 8 + i) * SP + s];
                acc[i][0] += p * v4.x;
                acc[i][1] += p * v4.y;
                acc[i][2] += p * v4.z;
                acc[i][3] += p * v4.w;
            }
        }
        __syncthreads();
    }

#pragma unroll
    for (int i = 0; i < 8; i++) {
        const int q = ty * 8 + i;
        const float inv = 1.f / lrow[i];
        float v0 = acc[i][0] * inv, v1 = acc[i][1] * inv;
        float v2 = acc[i][2] * inv, v3 = acc[i][3] * inv;
        __half h0, l0, h1, l1, h2, l2, h3, l3;
        split_act(v0, h0, l0); split_act(v1, h1, l1);
        split_act(v2, h2, l2); split_act(v3, h3, l3);
        size_t base = ((size_t)((q0 + q) * BATCH + b)) * D + h * DKH + tx * 4;
        *(__half2*)(ahi + base)     = __halves2half2(h0, h1);
        *(__half2*)(ahi + base + 2) = __halves2half2(h2, h3);
        *(__half2*)(alo + base)     = __halves2half2(l0, l1);
        *(__half2*)(alo + base + 2) = __halves2half2(l2, l3);
    }
}

// ---------------- fused GRU + LN + splits (one block per token) --------------
__global__ __launch_bounds__(256)
void gru_ln_split(float* __restrict__ px, const float* __restrict__ gate,
                  const float* __restrict__ bg,
                  const float* __restrict__ g, const float* __restrict__ b,
                  __half* __restrict__ cathi, __half* __restrict__ catlo,
                  __half* __restrict__ lnhi, __half* __restrict__ lnlo,
                  float* __restrict__ outf) {
    const int n = blockIdx.x;
    const int tid = threadIdx.x;
    const float* grow = gate + (size_t)n * D3;
    float vals[4];
    float s = 0.f, sq = 0.f;
#pragma unroll
    for (int k = 0; k < 4; k++) {
        const int j = tid + k * 256;
        float gr = grow[j];
        float gz = grow[D + j];
        float gh = grow[2 * D + j];
        float r = 1.f / (1.f + __expf(-gr));
        float z = 1.f / (1.f + __expf(-(gz - bg[j])));
        float hh = tanhf(gh * r);
        float xv = px[(size_t)n * D + j];
        float v = (1.f - z) * xv + z * hh;
        px[(size_t)n * D + j] = v;
        vals[k] = v;
        __half h, l; split_act(v, h, l);
        cathi[(size_t)n * D2 + j] = h;
        catlo[(size_t)n * D2 + j] = l;
        s += v; sq += v * v;
    }
    __shared__ float rs[256], rq[256];
    rs[tid] = s; rq[tid] = sq; __syncthreads();
    for (int off = 128; off > 0; off >>= 1) {
        if (tid < off) { rs[tid] += rs[tid + off]; rq[tid] += rq[tid + off]; }
        __syncthreads();
    }
    const float mu  = rs[0] * (1.f / D);
    const float var = rq[0] * (1.f / D) - mu * mu;
    const float inv = rsqrtf(var + 1e-6f);
#pragma unroll
    for (int k = 0; k < 4; k++) {
        const int j = tid + k * 256;
        float y = (vals[k] - mu) * inv * g[j] + b[j];
        if (outf) {
            outf[(size_t)n * D + j] = y;
        } else {
            __half h, l; split_act(y, h, l);
            lnhi[(size_t)n * D + j] = h;
            lnlo[(size_t)n * D + j] = l;
        }
    }
}

// ---------------- fused GELU+PE + LN + splits (layer-0 entry) ----------------
__global__ __launch_bounds__(256)
void gelu_pe_ln_split(float* __restrict__ px, const float* __restrict__ pe,
                      const float* __restrict__ g, const float* __restrict__ b,
                      __half* __restrict__ cathi, __half* __restrict__ catlo,
                      __half* __restrict__ lnhi, __half* __restrict__ lnlo) {
    const int n = blockIdx.x;
    const int t = n >> 1;
    const int tid = threadIdx.x;
    float vals[4];
    float s = 0.f, sq = 0.f;
#pragma unroll
    for (int k = 0; k < 4; k++) {
        const int j = tid + k * 256;
        float v = gelu_exact(px[(size_t)n * D + j]) + pe[(size_t)t * D + j];
        px[(size_t)n * D + j] = v;
        vals[k] = v;
        __half h, l; split_act(v, h, l);
        cathi[(size_t)n * D2 + j] = h;
        catlo[(size_t)n * D2 + j] = l;
        s += v; sq += v * v;
    }
    __shared__ float rs[256], rq[256];
    rs[tid] = s; rq[tid] = sq; __syncthreads();
    for (int off = 128; off > 0; off >>= 1) {
        if (tid < off) { rs[tid] += rs[tid + off]; rq[tid] += rq[tid + off]; }
        __syncthreads();
    }
    const float mu  = rs[0] * (1.f / D);
    const float var = rq[0] * (1.f / D) - mu * mu;
    const float inv = rsqrtf(var + 1e-6f);
#pragma unroll
    for (int k = 0; k < 4; k++) {
        const int j = tid + k * 256;
        float y = (vals[k] - mu) * inv * g[j] + b[j];
        __half h, l; split_act(y, h, l);
        lnhi[(size_t)n * D + j] = h;
        lnlo[(size_t)n * D + j] = l;
    }
}

// ---------------- f32 -> fp16 pair splits ----------------
__global__ void cvt_split_act(const float4* __restrict__ x,
                              __half2* __restrict__ hi, __half2* __restrict__ lo,
                              int n4) {
    int i = blockIdx.x * blockDim.x + threadIdx.x;
    if (i >= n4) return;
    float4 v = x[i];
    __half h0, l0, h1, l1, h2, l2, h3, l3;
    split_act(v.x, h0, l0); split_act(v.y, h1, l1);
    split_act(v.z, h2, l2); split_act(v.w, h3, l3);
    hi[2*i]   = __halves2half2(h0, h1);
    hi[2*i+1] = __halves2half2(h2, h3);
    lo[2*i]   = __halves2half2(l0, l1);
    lo[2*i+1] = __halves2half2(l2, l3);
}

__global__ void cvt_split_wgt(const float4* __restrict__ x,
                              __half2* __restrict__ hi, __half2* __restrict__ w2,
                              int n4) {
    int i = blockIdx.x * blockDim.x + threadIdx.x;
    if (i >= n4) return;
    float4 v = x[i];
    __half h0, l0, h1, l1, h2, l2, h3, l3;
    split_wgt(v.x, h0, l0); split_wgt(v.y, h1, l1);
    split_wgt(v.z, h2, l2); split_wgt(v.w, h3, l3);
    hi[2*i]   = __halves2half2(h0, h1);
    hi[2*i+1] = __halves2half2(h2, h3);
    w2[2*i]   = __halves2half2(l0, l1);
    w2[2*i+1] = __halves2half2(l2, l3);
}

// ---------------- driver ----------------
extern "C" void kernel_launch(void* const* d_in, const int* in_sizes, int n_in,
                              void* d_out, int out_size) {
    const float* x_in  = (const float*)d_in[0];
    const float* pe    = (const float*)d_in[1];
    const float* in_w  = (const float*)d_in[2];
    const float* in_b  = (const float*)d_in[3];
    const float* qkv_w = (const float*)d_in[4];
    const float* out_w = (const float*)d_in[5];
    const float* out_b = (const float*)d_in[6];
    const float* ln1_g = (const float*)d_in[7];
    const float* ln1_b = (const float*)d_in[8];
    const float* ln2_g = (const float*)d_in[9];
    const float* ln2_b = (const float*)d_in[10];
    const float* ff_w1 = (const float*)d_in[11];
    const float* ff_b1 = (const float*)d_in[12];
    const float* ff_w2 = (const float*)d_in[13];
    const float* ff_b2 = (const float*)d_in[14];
    const float* g1_w  = (const float*)d_in[15];
    const float* g1_bg = (const float*)d_in[16];
    const float* g2_w  = (const float*)d_in[17];
    const float* g2_bg = (const float*)d_in[18];
    const float* on_g  = (const float*)d_in[19];
    const float* on_b  = (const float*)d_in[20];

    float *px, *pqkv, *pgate;
    __half *chi, *clo, *lhi, *llo, *phi, *plo, *fhi, *flo, *xhi, *xlo;
    __half *w_in_h, *w_in_l, *w_qkv_h, *w_qkv_l, *w_out_h, *w_out_l;
    __half *w_f1_h, *w_f1_l, *w_f2_h, *w_f2_l, *w_g1_h, *w_g1_l, *w_g2_h, *w_g2_l;
    cudaGetSymbolAddress((void**)&px,    g_x);
    cudaGetSymbolAddress((void**)&pqkv,  g_qkv);
    cudaGetSymbolAddress((void**)&pgate, g_gate);
    cudaGetSymbolAddress((void**)&chi,   g_chi);  cudaGetSymbolAddress((void**)&clo,   g_clo);
    cudaGetSymbolAddress((void**)&lhi,   g_lhi);  cudaGetSymbolAddress((void**)&llo,   g_llo);
    cudaGetSymbolAddress((void**)&phi,   g_phi);  cudaGetSymbolAddress((void**)&plo,   g_plo);
    cudaGetSymbolAddress((void**)&fhi,   g_fhi);  cudaGetSymbolAddress((void**)&flo,   g_flo);
    cudaGetSymbolAddress((void**)&xhi,   g_xhi);  cudaGetSymbolAddress((void**)&xlo,   g_xlo);
    cudaGetSymbolAddress((void**)&w_in_h,  wb_in_hi);  cudaGetSymbolAddress((void**)&w_in_l,  wb_in_lo);
    cudaGetSymbolAddress((void**)&w_qkv_h, wb_qkv_hi); cudaGetSymbolAddress((void**)&w_qkv_l, wb_qkv_lo);
    cudaGetSymbolAddress((void**)&w_out_h, wb_out_hi); cudaGetSymbolAddress((void**)&w_out_l, wb_out_lo);
    cudaGetSymbolAddress((void**)&w_f1_h,  wb_f1_hi);  cudaGetSymbolAddress((void**)&w_f1_l,  wb_f1_lo);
    cudaGetSymbolAddress((void**)&w_f2_h,  wb_f2_hi);  cudaGetSymbolAddress((void**)&w_f2_l,  wb_f2_lo);
    cudaGetSymbolAddress((void**)&w_g1_h,  wb_g1_hi);  cudaGetSymbolAddress((void**)&w_g1_l,  wb_g1_lo);
    cudaGetSymbolAddress((void**)&w_g2_h,  wb_g2_hi);  cudaGetSymbolAddress((void**)&w_g2_l,  wb_g2_lo);

    cudaFuncSetAttribute(gemm_mma, cudaFuncAttributeMaxDynamicSharedMemorySize, SMEM_BYTES);
    cudaFuncSetAttribute(attn_flash, cudaFuncAttributeMaxDynamicSharedMemorySize, ATTN_SMEM);

    int nsm = 148;
    cudaDeviceGetAttribute(&nsm, cudaDevAttrMultiProcessorCount, 0);

    const int EW = 256;
    auto cvtgrid = [](int n) { return (n / 4 + 255) / 256; };

    // ---- weight splits (hi, W2) and input split (hi, A2) ----
    cvt_split_wgt<<<cvtgrid(D*D),        EW>>>((const float4*)in_w,  (__half2*)w_in_h,  (__half2*)w_in_l,  D*D/4);
    cvt_split_wgt<<<cvtgrid(LNUM*D3*D),  EW>>>((const float4*)qkv_w, (__half2*)w_qkv_h, (__half2*)w_qkv_l, LNUM*D3*D/4);
    cvt_split_wgt<<<cvtgrid(LNUM*D*D),   EW>>>((const float4*)out_w, (__half2*)w_out_h, (__half2*)w_out_l, LNUM*D*D/4);
    cvt_split_wgt<<<cvtgrid(LNUM*FFD*D), EW>>>((const float4*)ff_w1, (__half2*)w_f1_h,  (__half2*)w_f1_l,  LNUM*FFD*D/4);
    cvt_split_wgt<<<cvtgrid(LNUM*D*FFD), EW>>>((const float4*)ff_w2, (__half2*)w_f2_h,  (__half2*)w_f2_l,  LNUM*D*FFD/4);
    cvt_split_wgt<<<cvtgrid(LNUM*D3*D2), EW>>>((const float4*)g1_w,  (__half2*)w_g1_h,  (__half2*)w_g1_l,  LNUM*D3*D2/4);
    cvt_split_wgt<<<cvtgrid(LNUM*D3*D2), EW>>>((const float4*)g2_w,  (__half2*)w_g2_h,  (__half2*)w_g2_l,  LNUM*D3*D2/4);
    cvt_split_act<<<cvtgrid(NTOK*D),     EW>>>((const float4*)x_in,  (__half2*)xhi,     (__half2*)xlo,     NTOK*D/4);

    const int gxD  = D   / 128, ntD  = gxD  * (NTOK / 128);
    const int gxD3 = D3  / 128, ntD3 = gxD3 * (NTOK / 128);
    const int gxFF = FFD / 128, ntFF = gxFF * (NTOK / 128);
    const int cD   = ntD  < nsm ? ntD  : nsm;
    const int cD3  = ntD3 < nsm ? ntD3 : nsm;
    const int cFF  = ntFF < nsm ? ntFF : nsm;

    gemm_mma<<<cD, 256, SMEM_BYTES>>>(xhi, xlo, D, w_in_h, w_in_l, in_b, px, 0, 0, D, D, 0, gxD, ntD);
    gelu_pe_ln_split<<<NTOK, 256>>>(px, pe, ln1_g, ln1_b, chi, clo, lhi, llo);

    for (int l = 0; l < LNUM; l++) {
        const __half* qwh = w_qkv_h + (size_t)l*D3*D;  const __half* qwl = w_qkv_l + (size_t)l*D3*D;
        const __half* owh = w_out_h + (size_t)l*D*D;   const __half* owl = w_out_l + (size_t)l*D*D;
        const __half* f1h = w_f1_h  + (size_t)l*FFD*D; const __half* f1l = w_f1_l  + (size_t)l*FFD*D;
        const __half* f2h = w_f2_h  + (size_t)l*D*FFD; const __half* f2l = w_f2_l  + (size_t)l*D*FFD;
        const __half* g1h = w_g1_h  + (size_t)l*D3*D2; const __half* g1l = w_g1_l  + (size_t)l*D3*D2;
        const __half* g2h = w_g2_h  + (size_t)l*D3*D2; const __half* g2l = w_g2_l  + (size_t)l*D3*D2;
        const float* ob  = out_b + (size_t)l*D;
        const float* l2g = ln2_g + (size_t)l*D;  const float* l2b = ln2_b + (size_t)l*D;
        const float* fb1 = ff_b1 + (size_t)l*FFD;
        const float* fb2 = ff_b2 + (size_t)l*D;
        const float* gb1 = g1_bg + (size_t)l*D;
        const float* gb2 = g2_bg + (size_t)l*D;
        const float* ng = (l + 1 < LNUM) ? ln1_g + (size_t)(l+1)*D : on_g;
        const float* nb = (l + 1 < LNUM) ? ln1_b + (size_t)(l+1)*D : on_b;
        float* fout = (l + 1 < LNUM) ? nullptr : (float*)d_out;

        // attention block
        gemm_mma<<<cD3, 256, SMEM_BYTES>>>(lhi, llo, D, qwh, qwl, nullptr, pqkv, 0, 0, D3, D, 0, gxD3, ntD3);
        attn_flash<<<dim3(TT/QTILE, BATCH*H), 256, ATTN_SMEM>>>(pqkv, phi, plo);
        gemm_mma<<<cD, 256, SMEM_BYTES>>>(phi, plo, D, owh, owl, ob, 0, chi + D, clo + D, D2, D, 2, gxD, ntD);
        gemm_mma<<<cD3, 256, SMEM_BYTES>>>(chi, clo, D2, g1h, g1l, nullptr, pgate, 0, 0, D3, D2, 0, gxD3, ntD3);
        gru_ln_split<<<NTOK, 256>>>(px, pgate, gb1, l2g, l2b, chi, clo, lhi, llo, nullptr);

        // feed-forward block
        gemm_mma<<<cFF, 256, SMEM_BYTES>>>(lhi, llo, D, f1h, f1l, fb1, 0, fhi, flo, FFD, D, 1, gxFF, ntFF);
        gemm_mma<<<cD, 256, SMEM_BYTES>>>(fhi, flo, FFD, f2h, f2l, fb2, 0, chi + D, clo + D, D2, FFD, 2, gxD, ntD);
        gemm_mma<<<cD3, 256, SMEM_BYTES>>>(chi, clo, D2, g2h, g2l, nullptr, pgate, 0, 0, D3, D2, 0, gxD3, ntD3);
        gru_ln_split<<<NTOK, 256>>>(px, pgate, gb2, ng, nb, chi, clo, lhi, llo, fout);
    }
}

// round 11
// speedup vs baseline: 1.3286x; 1.0520x over previous
#include <cuda_runtime.h>
#include <cuda_fp16.h>
#include <math.h>
#include <stdint.h>

// ---------------- problem constants ----------------
#define LNUM  6
#define D     1024
#define H     16
#define DKH   64
#define FFD   4096
#define TT    1024
#define BATCH 2
#define NTOK  2048
#define D3    3072
#define D2    2048
#define ATT_SCALE 0.125f
#define SCL   0.015625f        // 2^-6
#define SCLI  64.0f            // 2^6

#define SWZ(o) ((o) ^ (((o) >> 3) & 0x70))

// ---------------- scratch (device globals; no allocs allowed) ----------------
__device__ float g_x   [NTOK*D];     // residual stream (f32)
__device__ float g_qkv [NTOK*D3];
__device__ float g_gate[NTOK*D3];
__device__ __half g_chi[NTOK*D2],  g_clo[NTOK*D2];   // concat [x,y] hi / A2
__device__ __half g_lhi[NTOK*D],   g_llo[NTOK*D];    // LN output hi / A2
__device__ __half g_phi[NTOK*D],   g_plo[NTOK*D];    // attn output hi / A2
__device__ __half g_fhi[NTOK*FFD], g_flo[NTOK*FFD];  // FF hidden hi / A2
__device__ __half g_xhi[NTOK*D],   g_xlo[NTOK*D];    // input x split
__device__ __half wb_in_hi [D*D],        wb_in_lo [D*D];
__device__ __half wb_qkv_hi[LNUM*D3*D],  wb_qkv_lo[LNUM*D3*D];
__device__ __half wb_out_hi[LNUM*D*D],   wb_out_lo[LNUM*D*D];
__device__ __half wb_f1_hi [LNUM*FFD*D], wb_f1_lo [LNUM*FFD*D];
__device__ __half wb_f2_hi [LNUM*D*FFD], wb_f2_lo [LNUM*D*FFD];
__device__ __half wb_g1_hi [LNUM*D3*D2], wb_g1_lo [LNUM*D3*D2];
__device__ __half wb_g2_hi [LNUM*D3*D2], wb_g2_lo [LNUM*D3*D2];

// ---------------- PTX helpers (portable: sm_80-level) ----------------
__device__ __forceinline__ uint32_t smem_u32(const void* p) {
    uint32_t a;
    asm("{ .reg .u64 t; cvta.to.shared.u64 t, %1; cvt.u32.u64 %0, t; }" : "=r"(a) : "l"(p));
    return a;
}
__device__ __forceinline__ void cp16(uint32_t d, const void* g) {
    asm volatile("cp.async.cg.shared.global [%0], [%1], 16;" :: "r"(d), "l"(g));
}
__device__ __forceinline__ void ldm_x4(uint32_t* f, uint32_t addr) {
    asm volatile("ldmatrix.sync.aligned.m8n8.x4.shared.b16 {%0,%1,%2,%3}, [%4];"
                 : "=r"(f[0]), "=r"(f[1]), "=r"(f[2]), "=r"(f[3]) : "r"(addr));
}
__device__ __forceinline__ void mma16816(float* c, const uint32_t* a, uint32_t b0, uint32_t b1) {
    asm volatile(
        "mma.sync.aligned.m16n8k16.row.col.f32.f16.f16.f32 "
        "{%0,%1,%2,%3}, {%4,%5,%6,%7}, {%8,%9}, {%0,%1,%2,%3};"
        : "+f"(c[0]), "+f"(c[1]), "+f"(c[2]), "+f"(c[3])
        : "r"(a[0]), "r"(a[1]), "r"(a[2]), "r"(a[3]), "r"(b0), "r"(b1));
}
__device__ __forceinline__ float gelu_exact(float v) { return v * normcdff(v); }

// Activation split: hi = fp16(v); A2 = fp16((v - hi) + hi*2^-6)
__device__ __forceinline__ void split_act(float v, __half& h, __half& a2) {
    h = __float2half_rn(v);
    float lo = v - __half2float(h);
    a2 = __float2half_rn(fmaf(__half2float(h), SCL, lo));
}
// Weight split: hi = fp16(w); W2 = fp16(hi + (w - hi)*2^6)
__device__ __forceinline__ void split_wgt(float w, __half& h, __half& w2) {
    h = __float2half_rn(w);
    float lo = w - __half2float(h);
    w2 = __float2half_rn(fmaf(lo, SCLI, __half2float(h)));
}
// Final combine: C = acc1*(1 - 2^-6) + acc2
__device__ __forceinline__ float combine(float a1, float a2) {
    return fmaf(a1, 1.0f - SCL, a2);
}

// ---------------- fp16 2-MMA GEMM (persistent CTAs, cross-tile pipe) ---------
#define STAGE_B 65536
#define SMEM_BYTES (2*STAGE_B)

__global__ __launch_bounds__(256)
void gemm_mma(const __half* __restrict__ Ahi, const __half* __restrict__ A2p,
              int lda,
              const __half* __restrict__ Whi, const __half* __restrict__ W2p,
              const float* __restrict__ bias,
              float* __restrict__ Cf,
              __half* __restrict__ Chi, __half* __restrict__ Clo,
              int ldc, int K, int mode, int gx, int ntiles)
{
    extern __shared__ char smem[];
    const uint32_t sb = smem_u32(smem);
    const int tid  = threadIdx.x;
    const int wid  = tid >> 5;
    const int lane = tid & 31;
    const int wm   = wid >> 1;
    const int wn   = wid & 1;

    const int lr   = lane & 15;
    const int koff = (lane >> 4) << 4;
    uint32_t roffA[2], rxA[2], roffB[4], rxB[4];
#pragma unroll
    for (int i = 0; i < 2; i++) {
        int r = wm * 32 + i * 16 + lr;
        roffA[i] = r * 128; rxA[i] = (r & 7) << 4;
    }
#pragma unroll
    for (int j = 0; j < 4; j++) {
        int r = wn * 64 + j * 16 + lr;
        roffB[j] = r * 128; rxB[j] = (r & 7) << 4;
    }

    const int nch = K / 64;
    const int ldr = tid >> 3, ldc4 = tid & 7;

    auto issue = [&](int tt, int cc, int stage) {
        const int r0 = (tt / gx) * 128;
        const int c0 = (tt % gx) * 128;
        const int kbase = cc * 64;
        const uint32_t st = sb + stage * STAGE_B;
#pragma unroll
        for (int i = 0; i < 4; i++) {
            int r = ldr + i * 32;
            uint32_t off = SWZ((uint32_t)(r * 128 + ldc4 * 16));
            size_t sa = (size_t)(r0 + r) * lda + kbase + ldc4 * 8;
            size_t sw = (size_t)(c0 + r) * K   + kbase + ldc4 * 8;
            cp16(st +         off, Ahi + sa);
            cp16(st + 16384 + off, A2p + sa);
            cp16(st + 32768 + off, Whi + sw);
            cp16(st + 49152 + off, W2p + sw);
        }
        asm volatile("cp.async.commit_group;");
    };

    const int grid = (int)gridDim.x;
    int cur_stage = 0;
    issue(blockIdx.x, 0, 0);

    for (int t = blockIdx.x; t < ntiles; t += grid) {
        const int row0 = (t / gx) * 128;
        const int col0 = (t % gx) * 128;

        float acc1[2][8][4], acc2[2][8][4];
#pragma unroll
        for (int i = 0; i < 2; i++)
#pragma unroll
            for (int g = 0; g < 8; g++)
#pragma unroll
                for (int q = 0; q < 4; q++) { acc1[i][g][q] = 0.f; acc2[i][g][q] = 0.f; }

        for (int cc = 0; cc < nch; cc++) {
            asm volatile("cp.async.wait_group 0;");
            __syncthreads();
            const int nxt = cur_stage ^ 1;
            if (cc + 1 < nch)              issue(t, cc + 1, nxt);
            else if (t + grid < ntiles)    issue(t + grid, 0, nxt);

            const uint32_t AH = sb + cur_stage * STAGE_B;
            const uint32_t AL = AH + 16384;
            const uint32_t WHs = AH + 32768;
            const uint32_t WLs = AH + 49152;
#pragma unroll
            for (int ks = 0; ks < 4; ks++) {
                const uint32_t kb = ks * 32 + koff;
                uint32_t ah[2][4], a2[2][4];
#pragma unroll
                for (int i = 0; i < 2; i++) {
                    ldm_x4(ah[i], AH + roffA[i] + (kb ^ rxA[i]));
                    ldm_x4(a2[i], AL + roffA[i] + (kb ^ rxA[i]));
                }
#pragma unroll
                for (int j = 0; j < 4; j++) {
                    uint32_t bh[4], b2[4];
                    ldm_x4(bh, WHs + roffB[j] + (kb ^ rxB[j]));
                    ldm_x4(b2, WLs + roffB[j] + (kb ^ rxB[j]));
#pragma unroll
                    for (int i = 0; i < 2; i++) {
                        mma16816(acc1[i][j*2+0], ah[i], bh[0], bh[2]);
                        mma16816(acc1[i][j*2+1], ah[i], bh[1], bh[3]);
                        mma16816(acc2[i][j*2+0], a2[i], b2[0], b2[2]);
                        mma16816(acc2[i][j*2+1], a2[i], b2[1], b2[3]);
                    }
                }
            }
            cur_stage ^= 1;
        }

        const int rbase = row0 + wm * 32 + (lane >> 2);
        const int cbase = wn * 64 + (lane & 3) * 2;
#pragma unroll
        for (int i = 0; i < 2; i++) {
#pragma unroll
            for (int g = 0; g < 8; g++) {
                const int c  = cbase + g * 8;
                const int cg = col0 + c;
                const int r0 = rbase + i * 16;
                float b0 = bias ? bias[cg]     : 0.f;
                float b1 = bias ? bias[cg + 1] : 0.f;
                float v00 = combine(acc1[i][g][0], acc2[i][g][0]) + b0;
                float v01 = combine(acc1[i][g][1], acc2[i][g][1]) + b1;
                float v10 = combine(acc1[i][g][2], acc2[i][g][2]) + b0;
                float v11 = combine(acc1[i][g][3], acc2[i][g][3]) + b1;
                if (mode == 0) {
                    *(float2*)(Cf + (size_t)r0 * ldc + cg)     = make_float2(v00, v01);
                    *(float2*)(Cf + (size_t)(r0+8) * ldc + cg) = make_float2(v10, v11);
                } else {
                    if (mode == 1) {
                        v00 = gelu_exact(v00); v01 = gelu_exact(v01);
                        v10 = gelu_exact(v10); v11 = gelu_exact(v11);
                    }
                    __half h00, l00, h01, l01, h10, l10, h11, l11;
                    split_act(v00, h00, l00); split_act(v01, h01, l01);
                    split_act(v10, h10, l10); split_act(v11, h11, l11);
                    *(__half2*)(Chi + (size_t)r0 * ldc + cg)     = __halves2half2(h00, h01);
                    *(__half2*)(Chi + (size_t)(r0+8) * ldc + cg) = __halves2half2(h10, h11);
                    *(__half2*)(Clo + (size_t)r0 * ldc + cg)     = __halves2half2(l00, l01);
                    *(__half2*)(Clo + (size_t)(r0+8) * ldc + cg) = __halves2half2(l10, l11);
                }
            }
        }
    }
}

// ---------------- flash attention: QTILE=64 for 2 CTAs/SM --------------------
// Register softmax (4 rows/thread, half-warp shuffles). 70KB smem -> 2 CTAs
// co-resident per SM; 512-CTA grid with heavy q-tiles first.
#define QTILE 64
#define KTILE 64
#define QP 68
#define KP 68
#define VP 68
#define SP 68
#define AQ_OFF 0
#define AK_OFF (AQ_OFF + 64*QP)
#define AV_OFF (AK_OFF + 64*KP)
#define AS_OFF (AV_OFF + 64*VP)
#define ATTN_SMEM ((AS_OFF + 64*SP) * 4)

__global__ __launch_bounds__(256)
void attn_flash(const float* __restrict__ qkv,
                __half* __restrict__ ahi, __half* __restrict__ alo) {
    extern __shared__ float sm[];
    float* Qs = sm + AQ_OFF;
    float* Kt = sm + AK_OFF;
    float* Vs = sm + AV_OFF;
    float* Ss = sm + AS_OFF;

    const int tid = threadIdx.x;
    const int tx = tid & 15, ty = tid >> 4;
    const int bh = blockIdx.y;
    const int b  = bh >> 4;
    const int h  = bh & 15;
    const int qt = (int)gridDim.x - 1 - (int)blockIdx.x;   // heavy tiles first
    const int q0 = qt * QTILE;

    // load Q tile (64 rows x 64, pre-scaled): 4 float4 per thread
#pragma unroll
    for (int i = 0; i < 4; i++) {
        int idx = tid + i * 256;
        int r = idx >> 4, c = idx & 15;
        float4 v = *(const float4*)(qkv + ((size_t)((q0 + r) * BATCH + b)) * D3 + h * DKH + c * 4);
        v.x *= ATT_SCALE; v.y *= ATT_SCALE; v.z *= ATT_SCALE; v.w *= ATT_SCALE;
        *(float4*)(Qs + r * QP + c * 4) = v;
    }

    float acc[4][4];
    float mrow[4], lrow[4];
#pragma unroll
    for (int i = 0; i < 4; i++) {
        mrow[i] = -1e30f; lrow[i] = 0.f;
#pragma unroll
        for (int j = 0; j < 4; j++) acc[i][j] = 0.f;
    }

    __syncthreads();

    const int ntiles = qt + 1;

    for (int kt = 0; kt < ntiles; kt++) {
        const int s0 = kt * KTILE;
#pragma unroll
        for (int i = 0; i < 4; i++) {
            int idx = tid + i * 256;
            int r = idx >> 4, c = idx & 15;
            const float* base = qkv + ((size_t)((s0 + r) * BATCH + b)) * D3 + h * DKH + c * 4;
            float4 kv = *(const float4*)(base + D);
            float4 vv = *(const float4*)(base + 2 * D);
            Kt[(c*4+0) * KP + r] = kv.x;
            Kt[(c*4+1) * KP + r] = kv.y;
            Kt[(c*4+2) * KP + r] = kv.z;
            Kt[(c*4+3) * KP + r] = kv.w;
            *(float4*)(Vs + r * VP + c * 4) = vv;
        }
        __syncthreads();

        // ---- scores in registers: 4 q-rows x 4 keys per thread ----
        float sreg[4][4];
#pragma unroll
        for (int i = 0; i < 4; i++)
#pragma unroll
            for (int j = 0; j < 4; j++) sreg[i][j] = 0.f;
#pragma unroll 8
        for (int d = 0; d < 64; d++) {
            const float4 kq = *(const float4*)(Kt + d * KP + tx * 4);
#pragma unroll
            for (int i = 0; i < 4; i++) {
                float qv = Qs[(ty * 4 + i) * QP + d];
                sreg[i][0] += qv * kq.x;
                sreg[i][1] += qv * kq.y;
                sreg[i][2] += qv * kq.z;
                sreg[i][3] += qv * kq.w;
            }
        }
        // ---- causal mask ----
#pragma unroll
        for (int i = 0; i < 4; i++) {
            const int qg = q0 + ty * 4 + i;
            if (s0 + tx*4 + 0 > qg) sreg[i][0] = -1e30f;
            if (s0 + tx*4 + 1 > qg) sreg[i][1] = -1e30f;
            if (s0 + tx*4 + 2 > qg) sreg[i][2] = -1e30f;
            if (s0 + tx*4 + 3 > qg) sreg[i][3] = -1e30f;
        }

        // ---- online softmax in registers (half-warp shuffles) ----
        float frow[4];
#pragma unroll
        for (int i = 0; i < 4; i++) {
            float tmax = fmaxf(fmaxf(sreg[i][0], sreg[i][1]),
                               fmaxf(sreg[i][2], sreg[i][3]));
#pragma unroll
            for (int o = 8; o > 0; o >>= 1)
                tmax = fmaxf(tmax, __shfl_xor_sync(0xffffffffu, tmax, o));
            const float mn = fmaxf(mrow[i], tmax);
            frow[i] = __expf(mrow[i] - mn);
            mrow[i] = mn;
            float p0 = __expf(sreg[i][0] - mn);
            float p1 = __expf(sreg[i][1] - mn);
            float p2 = __expf(sreg[i][2] - mn);
            float p3 = __expf(sreg[i][3] - mn);
            float rs = p0 + p1 + p2 + p3;
#pragma unroll
            for (int o = 8; o > 0; o >>= 1)
                rs += __shfl_xor_sync(0xffffffffu, rs, o);
            lrow[i] = lrow[i] * frow[i] + rs;
            *(float4*)(Ss + (ty * 4 + i) * SP + tx * 4) = make_float4(p0, p1, p2, p3);
            acc[i][0] *= frow[i]; acc[i][1] *= frow[i];
            acc[i][2] *= frow[i]; acc[i][3] *= frow[i];
        }
        __syncthreads();

        // ---- P @ V ----
#pragma unroll 4
        for (int s = 0; s < 64; s++) {
            const float4 v4 = *(const float4*)(Vs + s * VP + tx * 4);
#pragma unroll
            for (int i = 0; i < 4; i++) {
                const float p = Ss[(ty * 4 + i) * SP + s];
                acc[i][0] += p * v4.x;
                acc[i][1] += p * v4.y;
                acc[i][2] += p * v4.z;
                acc[i][3] += p * v4.w;
            }
        }
        __syncthreads();
    }

#pragma unroll
    for (int i = 0; i < 4; i++) {
        const int q = ty * 4 + i;
        const float inv = 1.f / lrow[i];
        float v0 = acc[i][0] * inv, v1 = acc[i][1] * inv;
        float v2 = acc[i][2] * inv, v3 = acc[i][3] * inv;
        __half h0, l0, h1, l1, h2, l2, h3, l3;
        split_act(v0, h0, l0); split_act(v1, h1, l1);
        split_act(v2, h2, l2); split_act(v3, h3, l3);
        size_t base = ((size_t)((q0 + q) * BATCH + b)) * D + h * DKH + tx * 4;
        *(__half2*)(ahi + base)     = __halves2half2(h0, h1);
        *(__half2*)(ahi + base + 2) = __halves2half2(h2, h3);
        *(__half2*)(alo + base)     = __halves2half2(l0, l1);
        *(__half2*)(alo + base + 2) = __halves2half2(l2, l3);
    }
}

// ---------------- fused GRU + LN + splits (one block per token) --------------
__global__ __launch_bounds__(256)
void gru_ln_split(float* __restrict__ px, const float* __restrict__ gate,
                  const float* __restrict__ bg,
                  const float* __restrict__ g, const float* __restrict__ b,
                  __half* __restrict__ cathi, __half* __restrict__ catlo,
                  __half* __restrict__ lnhi, __half* __restrict__ lnlo,
                  float* __restrict__ outf) {
    const int n = blockIdx.x;
    const int tid = threadIdx.x;
    const float* grow = gate + (size_t)n * D3;
    float vals[4];
    float s = 0.f, sq = 0.f;
#pragma unroll
    for (int k = 0; k < 4; k++) {
        const int j = tid + k * 256;
        float gr = grow[j];
        float gz = grow[D + j];
        float gh = grow[2 * D + j];
        float r = 1.f / (1.f + __expf(-gr));
        float z = 1.f / (1.f + __expf(-(gz - bg[j])));
        float hh = tanhf(gh * r);
        float xv = px[(size_t)n * D + j];
        float v = (1.f - z) * xv + z * hh;
        px[(size_t)n * D + j] = v;
        vals[k] = v;
        __half h, l; split_act(v, h, l);
        cathi[(size_t)n * D2 + j] = h;
        catlo[(size_t)n * D2 + j] = l;
        s += v; sq += v * v;
    }
    __shared__ float rs[256], rq[256];
    rs[tid] = s; rq[tid] = sq; __syncthreads();
    for (int off = 128; off > 0; off >>= 1) {
        if (tid < off) { rs[tid] += rs[tid + off]; rq[tid] += rq[tid + off]; }
        __syncthreads();
    }
    const float mu  = rs[0] * (1.f / D);
    const float var = rq[0] * (1.f / D) - mu * mu;
    const float inv = rsqrtf(var + 1e-6f);
#pragma unroll
    for (int k = 0; k < 4; k++) {
        const int j = tid + k * 256;
        float y = (vals[k] - mu) * inv * g[j] + b[j];
        if (outf) {
            outf[(size_t)n * D + j] = y;
        } else {
            __half h, l; split_act(y, h, l);
            lnhi[(size_t)n * D + j] = h;
            lnlo[(size_t)n * D + j] = l;
        }
    }
}

// ---------------- fused GELU+PE + LN + splits (layer-0 entry) ----------------
__global__ __launch_bounds__(256)
void gelu_pe_ln_split(float* __restrict__ px, const float* __restrict__ pe,
                      const float* __restrict__ g, const float* __restrict__ b,
                      __half* __restrict__ cathi, __half* __restrict__ catlo,
                      __half* __restrict__ lnhi, __half* __restrict__ lnlo) {
    const int n = blockIdx.x;
    const int t = n >> 1;
    const int tid = threadIdx.x;
    float vals[4];
    float s = 0.f, sq = 0.f;
#pragma unroll
    for (int k = 0; k < 4; k++) {
        const int j = tid + k * 256;
        float v = gelu_exact(px[(size_t)n * D + j]) + pe[(size_t)t * D + j];
        px[(size_t)n * D + j] = v;
        vals[k] = v;
        __half h, l; split_act(v, h, l);
        cathi[(size_t)n * D2 + j] = h;
        catlo[(size_t)n * D2 + j] = l;
        s += v; sq += v * v;
    }
    __shared__ float rs[256], rq[256];
    rs[tid] = s; rq[tid] = sq; __syncthreads();
    for (int off = 128; off > 0; off >>= 1) {
        if (tid < off) { rs[tid] += rs[tid + off]; rq[tid] += rq[tid + off]; }
        __syncthreads();
    }
    const float mu  = rs[0] * (1.f / D);
    const float var = rq[0] * (1.f / D) - mu * mu;
    const float inv = rsqrtf(var + 1e-6f);
#pragma unroll
    for (int k = 0; k < 4; k++) {
        const int j = tid + k * 256;
        float y = (vals[k] - mu) * inv * g[j] + b[j];
        __half h, l; split_act(y, h, l);
        lnhi[(size_t)n * D + j] = h;
        lnlo[(size_t)n * D + j] = l;
    }
}

// ---------------- f32 -> fp16 pair splits ----------------
__global__ void cvt_split_act(const float4* __restrict__ x,
                              __half2* __restrict__ hi, __half2* __restrict__ lo,
                              int n4) {
    int i = blockIdx.x * blockDim.x + threadIdx.x;
    if (i >= n4) return;
    float4 v = x[i];
    __half h0, l0, h1, l1, h2, l2, h3, l3;
    split_act(v.x, h0, l0); split_act(v.y, h1, l1);
    split_act(v.z, h2, l2); split_act(v.w, h3, l3);
    hi[2*i]   = __halves2half2(h0, h1);
    hi[2*i+1] = __halves2half2(h2, h3);
    lo[2*i]   = __halves2half2(l0, l1);
    lo[2*i+1] = __halves2half2(l2, l3);
}

__global__ void cvt_split_wgt(const float4* __restrict__ x,
                              __half2* __restrict__ hi, __half2* __restrict__ w2,
                              int n4) {
    int i = blockIdx.x * blockDim.x + threadIdx.x;
    if (i >= n4) return;
    float4 v = x[i];
    __half h0, l0, h1, l1, h2, l2, h3, l3;
    split_wgt(v.x, h0, l0); split_wgt(v.y, h1, l1);
    split_wgt(v.z, h2, l2); split_wgt(v.w, h3, l3);
    hi[2*i]   = __halves2half2(h0, h1);
    hi[2*i+1] = __halves2half2(h2, h3);
    w2[2*i]   = __halves2half2(l0, l1);
    w2[2*i+1] = __halves2half2(l2, l3);
}

// ---------------- driver ----------------
extern "C" void kernel_launch(void* const* d_in, const int* in_sizes, int n_in,
                              void* d_out, int out_size) {
    const float* x_in  = (const float*)d_in[0];
    const float* pe    = (const float*)d_in[1];
    const float* in_w  = (const float*)d_in[2];
    const float* in_b  = (const float*)d_in[3];
    const float* qkv_w = (const float*)d_in[4];
    const float* out_w = (const float*)d_in[5];
    const float* out_b = (const float*)d_in[6];
    const float* ln1_g = (const float*)d_in[7];
    const float* ln1_b = (const float*)d_in[8];
    const float* ln2_g = (const float*)d_in[9];
    const float* ln2_b = (const float*)d_in[10];
    const float* ff_w1 = (const float*)d_in[11];
    const float* ff_b1 = (const float*)d_in[12];
    const float* ff_w2 = (const float*)d_in[13];
    const float* ff_b2 = (const float*)d_in[14];
    const float* g1_w  = (const float*)d_in[15];
    const float* g1_bg = (const float*)d_in[16];
    const float* g2_w  = (const float*)d_in[17];
    const float* g2_bg = (const float*)d_in[18];
    const float* on_g  = (const float*)d_in[19];
    const float* on_b  = (const float*)d_in[20];

    float *px, *pqkv, *pgate;
    __half *chi, *clo, *lhi, *llo, *phi, *plo, *fhi, *flo, *xhi, *xlo;
    __half *w_in_h, *w_in_l, *w_qkv_h, *w_qkv_l, *w_out_h, *w_out_l;
    __half *w_f1_h, *w_f1_l, *w_f2_h, *w_f2_l, *w_g1_h, *w_g1_l, *w_g2_h, *w_g2_l;
    cudaGetSymbolAddress((void**)&px,    g_x);
    cudaGetSymbolAddress((void**)&pqkv,  g_qkv);
    cudaGetSymbolAddress((void**)&pgate, g_gate);
    cudaGetSymbolAddress((void**)&chi,   g_chi);  cudaGetSymbolAddress((void**)&clo,   g_clo);
    cudaGetSymbolAddress((void**)&lhi,   g_lhi);  cudaGetSymbolAddress((void**)&llo,   g_llo);
    cudaGetSymbolAddress((void**)&phi,   g_phi);  cudaGetSymbolAddress((void**)&plo,   g_plo);
    cudaGetSymbolAddress((void**)&fhi,   g_fhi);  cudaGetSymbolAddress((void**)&flo,   g_flo);
    cudaGetSymbolAddress((void**)&xhi,   g_xhi);  cudaGetSymbolAddress((void**)&xlo,   g_xlo);
    cudaGetSymbolAddress((void**)&w_in_h,  wb_in_hi);  cudaGetSymbolAddress((void**)&w_in_l,  wb_in_lo);
    cudaGetSymbolAddress((void**)&w_qkv_h, wb_qkv_hi); cudaGetSymbolAddress((void**)&w_qkv_l, wb_qkv_lo);
    cudaGetSymbolAddress((void**)&w_out_h, wb_out_hi); cudaGetSymbolAddress((void**)&w_out_l, wb_out_lo);
    cudaGetSymbolAddress((void**)&w_f1_h,  wb_f1_hi);  cudaGetSymbolAddress((void**)&w_f1_l,  wb_f1_lo);
    cudaGetSymbolAddress((void**)&w_f2_h,  wb_f2_hi);  cudaGetSymbolAddress((void**)&w_f2_l,  wb_f2_lo);
    cudaGetSymbolAddress((void**)&w_g1_h,  wb_g1_hi);  cudaGetSymbolAddress((void**)&w_g1_l,  wb_g1_lo);
    cudaGetSymbolAddress((void**)&w_g2_h,  wb_g2_hi);  cudaGetSymbolAddress((void**)&w_g2_l,  wb_g2_lo);

    cudaFuncSetAttribute(gemm_mma, cudaFuncAttributeMaxDynamicSharedMemorySize, SMEM_BYTES);
    cudaFuncSetAttribute(attn_flash, cudaFuncAttributeMaxDynamicSharedMemorySize, ATTN_SMEM);

    int nsm = 148;
    cudaDeviceGetAttribute(&nsm, cudaDevAttrMultiProcessorCount, 0);

    const int EW = 256;
    auto cvtgrid = [](int n) { return (n / 4 + 255) / 256; };

    // ---- weight splits (hi, W2) and input split (hi, A2) ----
    cvt_split_wgt<<<cvtgrid(D*D),        EW>>>((const float4*)in_w,  (__half2*)w_in_h,  (__half2*)w_in_l,  D*D/4);
    cvt_split_wgt<<<cvtgrid(LNUM*D3*D),  EW>>>((const float4*)qkv_w, (__half2*)w_qkv_h, (__half2*)w_qkv_l, LNUM*D3*D/4);
    cvt_split_wgt<<<cvtgrid(LNUM*D*D),   EW>>>((const float4*)out_w, (__half2*)w_out_h, (__half2*)w_out_l, LNUM*D*D/4);
    cvt_split_wgt<<<cvtgrid(LNUM*FFD*D), EW>>>((const float4*)ff_w1, (__half2*)w_f1_h,  (__half2*)w_f1_l,  LNUM*FFD*D/4);
    cvt_split_wgt<<<cvtgrid(LNUM*D*FFD), EW>>>((const float4*)ff_w2, (__half2*)w_f2_h,  (__half2*)w_f2_l,  LNUM*D*FFD/4);
    cvt_split_wgt<<<cvtgrid(LNUM*D3*D2), EW>>>((const float4*)g1_w,  (__half2*)w_g1_h,  (__half2*)w_g1_l,  LNUM*D3*D2/4);
    cvt_split_wgt<<<cvtgrid(LNUM*D3*D2), EW>>>((const float4*)g2_w,  (__half2*)w_g2_h,  (__half2*)w_g2_l,  LNUM*D3*D2/4);
    cvt_split_act<<<cvtgrid(NTOK*D),     EW>>>((const float4*)x_in,  (__half2*)xhi,     (__half2*)xlo,     NTOK*D/4);

    const int gxD  = D   / 128, ntD  = gxD  * (NTOK / 128);
    const int gxD3 = D3  / 128, ntD3 = gxD3 * (NTOK / 128);
    const int gxFF = FFD / 128, ntFF = gxFF * (NTOK / 128);
    const int cD   = ntD  < nsm ? ntD  : nsm;
    const int cD3  = ntD3 < nsm ? ntD3 : nsm;
    const int cFF  = ntFF < nsm ? ntFF : nsm;

    gemm_mma<<<cD, 256, SMEM_BYTES>>>(xhi, xlo, D, w_in_h, w_in_l, in_b, px, 0, 0, D, D, 0, gxD, ntD);
    gelu_pe_ln_split<<<NTOK, 256>>>(px, pe, ln1_g, ln1_b, chi, clo, lhi, llo);

    for (int l = 0; l < LNUM; l++) {
        const __half* qwh = w_qkv_h + (size_t)l*D3*D;  const __half* qwl = w_qkv_l + (size_t)l*D3*D;
        const __half* owh = w_out_h + (size_t)l*D*D;   const __half* owl = w_out_l + (size_t)l*D*D;
        const __half* f1h = w_f1_h  + (size_t)l*FFD*D; const __half* f1l = w_f1_l  + (size_t)l*FFD*D;
        const __half* f2h = w_f2_h  + (size_t)l*D*FFD; const __half* f2l = w_f2_l  + (size_t)l*D*FFD;
        const __half* g1h = w_g1_h  + (size_t)l*D3*D2; const __half* g1l = w_g1_l  + (size_t)l*D3*D2;
        const __half* g2h = w_g2_h  + (size_t)l*D3*D2; const __half* g2l = w_g2_l  + (size_t)l*D3*D2;
        const float* ob  = out_b + (size_t)l*D;
        const float* l2g = ln2_g + (size_t)l*D;  const float* l2b = ln2_b + (size_t)l*D;
        const float* fb1 = ff_b1 + (size_t)l*FFD;
        const float* fb2 = ff_b2 + (size_t)l*D;
        const float* gb1 = g1_bg + (size_t)l*D;
        const float* gb2 = g2_bg + (size_t)l*D;
        const float* ng = (l + 1 < LNUM) ? ln1_g + (size_t)(l+1)*D : on_g;
        const float* nb = (l + 1 < LNUM) ? ln1_b + (size_t)(l+1)*D : on_b;
        float* fout = (l + 1 < LNUM) ? nullptr : (float*)d_out;

        // attention block
        gemm_mma<<<cD3, 256, SMEM_BYTES>>>(lhi, llo, D, qwh, qwl, nullptr, pqkv, 0, 0, D3, D, 0, gxD3, ntD3);
        attn_flash<<<dim3(TT/QTILE, BATCH*H), 256, ATTN_SMEM>>>(pqkv, phi, plo);
        gemm_mma<<<cD, 256, SMEM_BYTES>>>(phi, plo, D, owh, owl, ob, 0, chi + D, clo + D, D2, D, 2, gxD, ntD);
        gemm_mma<<<cD3, 256, SMEM_BYTES>>>(chi, clo, D2, g1h, g1l, nullptr, pgate, 0, 0, D3, D2, 0, gxD3, ntD3);
        gru_ln_split<<<NTOK, 256>>>(px, pgate, gb1, l2g, l2b, chi, clo, lhi, llo, nullptr);

        // feed-forward block
        gemm_mma<<<cFF, 256, SMEM_BYTES>>>(lhi, llo, D, f1h, f1l, fb1, 0, fhi, flo, FFD, D, 1, gxFF, ntFF);
        gemm_mma<<<cD, 256, SMEM_BYTES>>>(fhi, flo, FFD, f2h, f2l, fb2, 0, chi + D, clo + D, D2, FFD, 2, gxD, ntD);
        gemm_mma<<<cD3, 256, SMEM_BYTES>>>(chi, clo, D2, g2h, g2l, nullptr, pgate, 0, 0, D3, D2, 0, gxD3, ntD3);
        gru_ln_split<<<NTOK, 256>>>(px, pgate, gb2, ng, nb, chi, clo, lhi, llo, fout);
    }
}